// round 3
// baseline (speedup 1.0000x reference)
#include <cuda_runtime.h>
#include <math.h>

// Problem constants
#define Bq  4
#define Sq  1024
#define Dm  1024
#define NHh 16
#define DHh 64
#define DIf 4096
#define EPS 1e-5f

// ---------------- scratch (static device globals; no allocations) ----------
__device__ float g_q [Bq*Sq*Dm];
__device__ float g_k [Bq*Sq*Dm];
__device__ float g_v [Bq*Sq*Dm];
__device__ float g_r [Bq*Sq*Dm];
__device__ float g_qw[Bq*Sq*Dm];
__device__ float g_qr[Bq*Sq*Dm];
__device__ float g_ac[(size_t)Bq*NHh*Sq*Sq];   // scores -> probs (in place)
__device__ float g_bd[(size_t)Bq*NHh*Sq*Sq];   // raw bd (pre rel_shift)
__device__ float g_av[Bq*Sq*Dm];
__device__ float g_ao[Bq*Sq*Dm];
__device__ float g_x [Bq*Sq*Dm];
__device__ float g_h [Bq*Sq*DIf];
__device__ float g_f [Bq*Sq*Dm];

// ---------------- generic tiled SGEMM -------------------------------------
// C[M,N] = A[M,K] @ op(B), op(B) = B[K,N] (TB=false) or B[N,K]^T (TB=true)
// Batched: blockIdx.z = g; per-matrix offset = (g/nh)*off1 + (g%nh)*off2.
// Requires: M % 128 == 0, N % 64 == 0, K % 16 == 0 (true for all calls here).
#define BM 128
#define BN 64
#define BK 16

template<bool TB, bool RELU, bool HASBIAS>
__global__ void __launch_bounds__(256)
gemm_kernel(const float* __restrict__ A, const float* __restrict__ B,
            float* __restrict__ C, const float* __restrict__ bias,
            int M, int N, int K, int lda, int ldb, int ldc,
            long offA1, long offA2, long offB1, long offB2,
            long offC1, long offC2, int nh)
{
    __shared__ float As[BM][BK + 1];
    __shared__ float Bs[BK][BN + 4];

    const int g = blockIdx.z;
    const float* Ab = A + (long)(g / nh) * offA1 + (long)(g % nh) * offA2;
    const float* Bb = B + (long)(g / nh) * offB1 + (long)(g % nh) * offB2;
    float*       Cb = C + (long)(g / nh) * offC1 + (long)(g % nh) * offC2;

    const int m0 = blockIdx.y * BM;
    const int n0 = blockIdx.x * BN;
    const int tid = threadIdx.x;
    const int tx = tid & 15;        // 16 column groups (4 cols each)
    const int ty = tid >> 4;        // 16 row groups    (8 rows each)

    float acc[8][4];
    #pragma unroll
    for (int i = 0; i < 8; i++)
        #pragma unroll
        for (int j = 0; j < 4; j++) acc[i][j] = 0.f;

    for (int k0 = 0; k0 < K; k0 += BK) {
        // A tile: 128x16
        #pragma unroll
        for (int i = 0; i < 8; i++) {
            int e = tid + i * 256;
            int row = e >> 4, col = e & 15;
            As[row][col] = Ab[(long)(m0 + row) * lda + k0 + col];
        }
        // B tile: 16x64 (from B or B^T)
        if (!TB) {
            #pragma unroll
            for (int i = 0; i < 4; i++) {
                int e = tid + i * 256;
                int row = e >> 6, col = e & 63;
                Bs[row][col] = Bb[(long)(k0 + row) * ldb + n0 + col];
            }
        } else {
            #pragma unroll
            for (int i = 0; i < 4; i++) {
                int e = tid + i * 256;
                int row = e >> 4, col = e & 15;   // row = n index, col = k index
                Bs[col][row] = Bb[(long)(n0 + row) * ldb + k0 + col];
            }
        }
        __syncthreads();

        #pragma unroll
        for (int kk = 0; kk < BK; kk++) {
            float4 bv = *(const float4*)&Bs[kk][tx * 4];
            #pragma unroll
            for (int i = 0; i < 8; i++) {
                float a = As[ty * 8 + i][kk];
                acc[i][0] += a * bv.x;
                acc[i][1] += a * bv.y;
                acc[i][2] += a * bv.z;
                acc[i][3] += a * bv.w;
            }
        }
        __syncthreads();
    }

    #pragma unroll
    for (int i = 0; i < 8; i++) {
        long crow = (long)(m0 + ty * 8 + i) * ldc + n0 + tx * 4;
        #pragma unroll
        for (int j = 0; j < 4; j++) {
            float v = acc[i][j];
            if (HASBIAS) v += bias[n0 + tx * 4 + j];
            if (RELU)    v = fmaxf(v, 0.f);
            Cb[crow + j] = v;
        }
    }
}

// ---------------- reductions ----------------------------------------------
__device__ __forceinline__ float warpSum(float v) {
    #pragma unroll
    for (int o = 16; o > 0; o >>= 1) v += __shfl_xor_sync(0xffffffffu, v, o);
    return v;
}
__device__ __forceinline__ float warpMax(float v) {
    #pragma unroll
    for (int o = 16; o > 0; o >>= 1) v = fmaxf(v, __shfl_xor_sync(0xffffffffu, v, o));
    return v;
}
__device__ float blockSum(float v) {
    __shared__ float red[8];
    __syncthreads();
    int lane = threadIdx.x & 31, wid = threadIdx.x >> 5;
    v = warpSum(v);
    if (lane == 0) red[wid] = v;
    __syncthreads();
    if (wid == 0) {
        float t = (lane < 8) ? red[lane] : 0.f;
        t = warpSum(t);
        if (lane == 0) red[0] = t;
    }
    __syncthreads();
    return red[0];
}
__device__ float blockMax(float v) {
    __shared__ float red[8];
    __syncthreads();
    int lane = threadIdx.x & 31, wid = threadIdx.x >> 5;
    v = warpMax(v);
    if (lane == 0) red[wid] = v;
    __syncthreads();
    if (wid == 0) {
        float t = (lane < 8) ? red[lane] : -1e30f;
        t = warpMax(t);
        if (lane == 0) red[0] = t;
    }
    __syncthreads();
    return red[0];
}

// ---------------- q + bias broadcast ---------------------------------------
__global__ void addbias2_kernel(const float* __restrict__ q,
                                const float* __restrict__ wb,
                                const float* __restrict__ rb,
                                float* __restrict__ qw,
                                float* __restrict__ qr)
{
    int t = blockIdx.x * blockDim.x + threadIdx.x;
    float v = q[t];
    int c = t & (Dm - 1);           // h*64 + d
    qw[t] = v + wb[c];
    qr[t] = v + rb[c];
}

// ---------------- fused rel_shift + mask + scale + softmax (in-place) ------
// One block per score row (g = b*NH + h, query i).
// score[i][j] = (ac[i][j] + bd_raw[i][S-1+j-i]) * scale  for j <= i, else -inf.
__global__ void softmax_kernel(float* __restrict__ ac, const float* __restrict__ bd)
{
    const long row = blockIdx.x;
    const int  i   = (int)(row & (Sq - 1));
    const long base = row * Sq;

    __shared__ float sbuf[Sq];
    const float scale = 0.125f;     // 1/sqrt(64)
    const int tid = threadIdx.x;

    float lmax = -1e30f;
    for (int j = tid; j < Sq; j += blockDim.x) {
        float s = -1e30f;
        if (j <= i)
            s = (ac[base + j] + bd[base + (Sq - 1 + j - i)]) * scale;
        sbuf[j] = s;
        lmax = fmaxf(lmax, s);
    }
    float rmax = blockMax(lmax);

    float lsum = 0.f;
    for (int j = tid; j < Sq; j += blockDim.x) {
        float e = (j <= i) ? __expf(sbuf[j] - rmax) : 0.f;
        sbuf[j] = e;
        lsum += e;
    }
    float rsum = blockSum(lsum);
    float inv = 1.f / rsum;

    for (int j = tid; j < Sq; j += blockDim.x)
        ac[base + j] = sbuf[j] * inv;
}

// ---------------- fused residual + LayerNorm --------------------------------
__global__ void ln_kernel(const float* __restrict__ a, const float* __restrict__ b,
                          const float* __restrict__ gam, const float* __restrict__ bet,
                          float* __restrict__ out)
{
    const long row = blockIdx.x;
    const long base = row * Dm;
    __shared__ float sbuf[Dm];
    const int tid = threadIdx.x;

    float ls = 0.f;
    for (int j = tid; j < Dm; j += blockDim.x) {
        float x = a[base + j] + b[base + j];
        sbuf[j] = x;
        ls += x;
    }
    float mu = blockSum(ls) * (1.f / Dm);

    float lv = 0.f;
    for (int j = tid; j < Dm; j += blockDim.x) {
        float d = sbuf[j] - mu;
        lv += d * d;
    }
    float var = blockSum(lv) * (1.f / Dm);
    float inv = rsqrtf(var + EPS);

    for (int j = tid; j < Dm; j += blockDim.x)
        out[base + j] = (sbuf[j] - mu) * inv * gam[j] + bet[j];
}

// ---------------- launch ----------------------------------------------------
extern "C" void kernel_launch(void* const* d_in, const int* in_sizes, int n_in,
                              void* d_out, int out_size)
{
    const float* w      = (const float*)d_in[0];
    const float* r      = (const float*)d_in[1];
    const float* w_bias = (const float*)d_in[2];
    const float* r_bias = (const float*)d_in[3];
    const float* Wq     = (const float*)d_in[4];
    const float* Wk     = (const float*)d_in[5];
    const float* Wv     = (const float*)d_in[6];
    const float* Wr     = (const float*)d_in[7];
    const float* Wo     = (const float*)d_in[8];
    const float* ln1g   = (const float*)d_in[9];
    const float* ln1b   = (const float*)d_in[10];
    const float* W1     = (const float*)d_in[11];
    const float* b1     = (const float*)d_in[12];
    const float* W2     = (const float*)d_in[13];
    const float* b2     = (const float*)d_in[14];
    const float* ln2g   = (const float*)d_in[15];
    const float* ln2b   = (const float*)d_in[16];
    float* out = (float*)d_out;

    float *q, *k, *v, *rr, *qw, *qr, *ac, *bd, *av, *ao, *x, *h, *f;
    cudaGetSymbolAddress((void**)&q,  g_q);
    cudaGetSymbolAddress((void**)&k,  g_k);
    cudaGetSymbolAddress((void**)&v,  g_v);
    cudaGetSymbolAddress((void**)&rr, g_r);
    cudaGetSymbolAddress((void**)&qw, g_qw);
    cudaGetSymbolAddress((void**)&qr, g_qr);
    cudaGetSymbolAddress((void**)&ac, g_ac);
    cudaGetSymbolAddress((void**)&bd, g_bd);
    cudaGetSymbolAddress((void**)&av, g_av);
    cudaGetSymbolAddress((void**)&ao, g_ao);
    cudaGetSymbolAddress((void**)&x,  g_x);
    cudaGetSymbolAddress((void**)&h,  g_h);
    cudaGetSymbolAddress((void**)&f,  g_f);

    const dim3 blk(256);
    const int M = Bq * Sq;                     // 4096

    // Projections: [4096,1024] @ [1024,1024]
    dim3 gp(Dm / BN, M / BM, 1);               // (16, 32)
    gemm_kernel<false,false,false><<<gp, blk>>>(w,  Wq, q,  nullptr, M, Dm, Dm, Dm, Dm, Dm, 0,0,0,0,0,0,1);
    gemm_kernel<false,false,false><<<gp, blk>>>(w,  Wk, k,  nullptr, M, Dm, Dm, Dm, Dm, Dm, 0,0,0,0,0,0,1);
    gemm_kernel<false,false,false><<<gp, blk>>>(w,  Wv, v,  nullptr, M, Dm, Dm, Dm, Dm, Dm, 0,0,0,0,0,0,1);
    gemm_kernel<false,false,false><<<gp, blk>>>(r,  Wr, rr, nullptr, M, Dm, Dm, Dm, Dm, Dm, 0,0,0,0,0,0,1);

    // q + w_bias / q + r_bias
    addbias2_kernel<<<(Bq*Sq*Dm)/256, blk>>>(q, w_bias, r_bias, qw, qr);

    // Batched NT attention scores: per (b,h): [1024,64] @ [1024,64]^T
    dim3 ga(Sq / BN, Sq / BM, Bq * NHh);       // (16, 8, 64)
    gemm_kernel<true,false,false><<<ga, blk>>>(qw, k, ac, nullptr,
        Sq, Sq, DHh, Dm, Dm, Sq,
        (long)Sq*Dm, 64, (long)Sq*Dm, 64, (long)NHh*Sq*Sq, (long)Sq*Sq, NHh);
    gemm_kernel<true,false,false><<<ga, blk>>>(qr, rr, bd, nullptr,
        Sq, Sq, DHh, Dm, Dm, Sq,
        (long)Sq*Dm, 64, (long)Sq*Dm, 64, (long)NHh*Sq*Sq, (long)Sq*Sq, NHh);

    // rel_shift + causal mask + scale + softmax (probs written into ac)
    softmax_kernel<<<Bq * NHh * Sq, blk>>>(ac, bd);

    // attn_vec = prob @ v  (batched NN, N=64)
    dim3 gv(DHh / BN, Sq / BM, Bq * NHh);      // (1, 8, 64)
    gemm_kernel<false,false,false><<<gv, blk>>>(ac, v, av, nullptr,
        Sq, DHh, Sq, Sq, Dm, Dm,
        (long)NHh*Sq*Sq, (long)Sq*Sq, (long)Sq*Dm, 64, (long)Sq*Dm, 64, NHh);

    // attn_out = attn_vec @ Wo
    gemm_kernel<false,false,false><<<gp, blk>>>(av, Wo, ao, nullptr, M, Dm, Dm, Dm, Dm, Dm, 0,0,0,0,0,0,1);

    // x = LN(w + attn_out)
    ln_kernel<<<M, blk>>>(w, ao, ln1g, ln1b, x);

    // FFN: h = relu(x @ W1 + b1); f = h @ W2 + b2
    dim3 gf1(DIf / BN, M / BM, 1);             // (64, 32)
    gemm_kernel<false,true, true ><<<gf1, blk>>>(x, W1, h, b1, M, DIf, Dm,  Dm,  DIf, DIf, 0,0,0,0,0,0,1);
    gemm_kernel<false,false,true ><<<gp,  blk>>>(h, W2, f, b2, M, Dm,  DIf, DIf, Dm,  Dm,  0,0,0,0,0,0,1);

    // out = LN(x + f)
    ln_kernel<<<M, blk>>>(x, f, ln2g, ln2b, out);
}

// round 4
// speedup vs baseline: 1.1755x; 1.1755x over previous
#include <cuda_runtime.h>
#include <math.h>

// Problem constants
#define Bq  4
#define Sq  1024
#define Dm  1024
#define NHh 16
#define DHh 64
#define DIf 4096
#define EPS 1e-5f

// ---------------- scratch (static device globals; no allocations) ----------
__device__ float g_q [Bq*Sq*Dm];
__device__ float g_k [Bq*Sq*Dm];
__device__ float g_v [Bq*Sq*Dm];
__device__ float g_r [Bq*Sq*Dm];
__device__ float g_qw[Bq*Sq*Dm];
__device__ float g_qr[Bq*Sq*Dm];
__device__ float g_ac[(size_t)Bq*NHh*Sq*Sq];   // scores -> probs (in place)
__device__ float g_bd[(size_t)Bq*NHh*Sq*Sq];   // raw bd (pre rel_shift)
__device__ float g_av[Bq*Sq*Dm];
__device__ float g_ao[Bq*Sq*Dm];
__device__ float g_x [Bq*Sq*Dm];
__device__ float g_h [Bq*Sq*DIf];
__device__ float g_f [Bq*Sq*Dm];

// ---------------- tf32 helpers ----------------------------------------------
__device__ __forceinline__ unsigned f2tf(float v) {
    unsigned r;
    asm("cvt.rna.tf32.f32 %0, %1;" : "=r"(r) : "f"(v));
    return r;
}

__device__ __forceinline__ void mma_tf32(float* d, const uint4& a, const uint2& b) {
    asm volatile(
        "mma.sync.aligned.m16n8k8.row.col.f32.tf32.tf32.f32 "
        "{%0,%1,%2,%3}, {%4,%5,%6,%7}, {%8,%9}, {%0,%1,%2,%3};"
        : "+f"(d[0]), "+f"(d[1]), "+f"(d[2]), "+f"(d[3])
        : "r"(a.x), "r"(a.y), "r"(a.z), "r"(a.w), "r"(b.x), "r"(b.y));
}

// ---------------- TF32 tensor-core GEMM --------------------------------------
// C[M,N] = A[M,K] @ op(B); op(B) = B[K,N] (TB=false) or B[N,K]^T (TB=true)
// Block tile: 128 x BN, BK=16. Warp tile 64x32 (4x4 m16n8k8).
// Warps = 2*(BN/32); threads = BN*2. BN in {64,128}.
// Requires M%128==0, N%BN==0, K%16==0, lda/ldb mult of 4, 16B-aligned bases.
template<int BN, bool TB, bool RELU, bool HASBIAS>
__global__ void __launch_bounds__(BN*2)
tgemm(const float* __restrict__ A, const float* __restrict__ B,
      float* __restrict__ C, const float* __restrict__ bias,
      int M, int N, int K, int lda, int ldb, int ldc,
      long offA1, long offA2, long offB1, long offB2,
      long offC1, long offC2, int nh)
{
    constexpr int BM = 128;
    constexpr int BK = 16;
    constexpr int THREADS = BN * 2;
    constexpr int NT = BN / 8;                 // n8 tiles per block
    constexpr int A_IT = 512 / THREADS;        // float4 loads of A per thread
    constexpr int B_IT = (4 * BN) / THREADS;   // float4 loads of B per thread (==2)

    // Fragment-permuted smem, double buffered.
    // A: [mt(8)][ks(2)][lane(32)][reg(4)]  B: [ks(2)][nt(NT)][lane(32)][reg(2)]
    __shared__ __align__(16) float As[2][8 * 2 * 32 * 4];
    __shared__ __align__(16) float Bs[2][2 * NT * 32 * 2];

    const int g = blockIdx.z;
    const float* Ab = A + (long)(g / nh) * offA1 + (long)(g % nh) * offA2;
    const float* Bb = B + (long)(g / nh) * offB1 + (long)(g % nh) * offB2;
    float*       Cb = C + (long)(g / nh) * offC1 + (long)(g % nh) * offC2;

    const int m0 = blockIdx.y * BM;
    const int n0 = blockIdx.x * BN;
    const int tid  = threadIdx.x;
    const int lane = tid & 31;
    const int wid  = tid >> 5;
    const int warp_m = wid & 1;     // 2 warps along M
    const int warp_n = wid >> 1;    // BN/32 warps along N

    float acc[4][4][4];
    #pragma unroll
    for (int i = 0; i < 4; i++)
        #pragma unroll
        for (int j = 0; j < 4; j++)
            #pragma unroll
            for (int l = 0; l < 4; l++) acc[i][j][l] = 0.f;

    float4 a_stage[A_IT];
    float4 b_stage[B_IT];

    const int ntiles = K / BK;

    // ---- gmem loads into registers ----
    auto loadA = [&](int k0) {
        #pragma unroll
        for (int i = 0; i < A_IT; i++) {
            int e = tid + i * THREADS;
            int row = e >> 2, kk = (e & 3) << 2;
            a_stage[i] = *(const float4*)&Ab[(long)(m0 + row) * lda + k0 + kk];
        }
    };
    auto loadB = [&](int k0) {
        #pragma unroll
        for (int i = 0; i < B_IT; i++) {
            int e = tid + i * THREADS;
            if (!TB) {
                int kk = e / (BN / 4), n = (e % (BN / 4)) * 4;
                b_stage[i] = *(const float4*)&Bb[(long)(k0 + kk) * ldb + n0 + n];
            } else {
                int n = e >> 2, kk = (e & 3) << 2;
                b_stage[i] = *(const float4*)&Bb[(long)(n0 + n) * ldb + k0 + kk];
            }
        }
    };

    // ---- smem stores (fragment-permuted, tf32-converted) ----
    auto storeA = [&](int buf) {
        #pragma unroll
        for (int i = 0; i < A_IT; i++) {
            int e = tid + i * THREADS;
            int row = e >> 2, kk = (e & 3) << 2;
            int mt = row >> 4, r = row & 15;
            int ks = kk >> 3;
            int regb = (r >= 8 ? 1 : 0) + (((kk & 7) >= 4) ? 2 : 0);
            int lane0 = (r & 7) * 4;
            unsigned* base = (unsigned*)&As[buf][(mt * 2 + ks) * 128];
            const float* v = (const float*)&a_stage[i];
            #pragma unroll
            for (int j = 0; j < 4; j++)
                base[(lane0 + j) * 4 + regb] = f2tf(v[j]);
        }
    };
    auto storeB = [&](int buf) {
        #pragma unroll
        for (int i = 0; i < B_IT; i++) {
            int e = tid + i * THREADS;
            const float* v = (const float*)&b_stage[i];
            if (!TB) {
                int kk = e / (BN / 4), n = (e % (BN / 4)) * 4;
                int ks = kk >> 3, nt = n >> 3, reg = ((kk & 7) >= 4);
                unsigned* base = (unsigned*)&Bs[buf][(ks * NT + nt) * 64];
                #pragma unroll
                for (int j = 0; j < 4; j++) {
                    int ln = ((n & 7) + j) * 4 + (kk & 3);
                    base[ln * 2 + reg] = f2tf(v[j]);
                }
            } else {
                int n = e >> 2, kk = (e & 3) << 2;
                int ks = kk >> 3, nt = n >> 3, reg = ((kk & 7) >= 4);
                unsigned* base = (unsigned*)&Bs[buf][(ks * NT + nt) * 64];
                int ln0 = (n & 7) * 4;
                #pragma unroll
                for (int j = 0; j < 4; j++)
                    base[(ln0 + j) * 2 + reg] = f2tf(v[j]);
            }
        }
    };

    // ---- compute one BK tile from smem ----
    auto compute = [&](int buf) {
        #pragma unroll
        for (int ks = 0; ks < 2; ks++) {
            uint4 af[4];
            #pragma unroll
            for (int mt = 0; mt < 4; mt++) {
                int gmt = warp_m * 4 + mt;
                af[mt] = *(const uint4*)&As[buf][((gmt * 2 + ks) * 32 + lane) * 4];
            }
            uint2 bf[4];
            #pragma unroll
            for (int nt = 0; nt < 4; nt++) {
                int gnt = warp_n * 4 + nt;
                bf[nt] = *(const uint2*)&Bs[buf][((ks * NT + gnt) * 32 + lane) * 2];
            }
            #pragma unroll
            for (int mt = 0; mt < 4; mt++)
                #pragma unroll
                for (int nt = 0; nt < 4; nt++)
                    mma_tf32(acc[mt][nt], af[mt], bf[nt]);
        }
    };

    // ---- main loop: double-buffered ----
    loadA(0); loadB(0);
    storeA(0); storeB(0);
    for (int t = 0; t < ntiles; t++) {
        __syncthreads();
        int buf = t & 1;
        if (t + 1 < ntiles) { loadA((t + 1) * BK); loadB((t + 1) * BK); }
        compute(buf);
        if (t + 1 < ntiles) { storeA(buf ^ 1); storeB(buf ^ 1); }
    }

    // ---- epilogue ----
    #pragma unroll
    for (int mt = 0; mt < 4; mt++) {
        int rbase = m0 + warp_m * 64 + mt * 16 + (lane >> 2);
        #pragma unroll
        for (int nt = 0; nt < 4; nt++) {
            int cbase = n0 + warp_n * 32 + nt * 8 + (lane & 3) * 2;
            float* d = acc[mt][nt];
            float b0 = 0.f, b1 = 0.f;
            if (HASBIAS) { b0 = bias[cbase]; b1 = bias[cbase + 1]; }
            float v0 = d[0] + b0, v1 = d[1] + b1;
            float v2 = d[2] + b0, v3 = d[3] + b1;
            if (RELU) {
                v0 = fmaxf(v0, 0.f); v1 = fmaxf(v1, 0.f);
                v2 = fmaxf(v2, 0.f); v3 = fmaxf(v3, 0.f);
            }
            *(float2*)&Cb[(long)rbase * ldc + cbase]       = make_float2(v0, v1);
            *(float2*)&Cb[(long)(rbase + 8) * ldc + cbase] = make_float2(v2, v3);
        }
    }
}

// ---------------- reductions ----------------------------------------------
__device__ __forceinline__ float warpSum(float v) {
    #pragma unroll
    for (int o = 16; o > 0; o >>= 1) v += __shfl_xor_sync(0xffffffffu, v, o);
    return v;
}
__device__ __forceinline__ float warpMax(float v) {
    #pragma unroll
    for (int o = 16; o > 0; o >>= 1) v = fmaxf(v, __shfl_xor_sync(0xffffffffu, v, o));
    return v;
}
__device__ float blockSum(float v) {
    __shared__ float red[8];
    __syncthreads();
    int lane = threadIdx.x & 31, wid = threadIdx.x >> 5;
    v = warpSum(v);
    if (lane == 0) red[wid] = v;
    __syncthreads();
    if (wid == 0) {
        float t = (lane < 8) ? red[lane] : 0.f;
        t = warpSum(t);
        if (lane == 0) red[0] = t;
    }
    __syncthreads();
    return red[0];
}
__device__ float blockMax(float v) {
    __shared__ float red[8];
    __syncthreads();
    int lane = threadIdx.x & 31, wid = threadIdx.x >> 5;
    v = warpMax(v);
    if (lane == 0) red[wid] = v;
    __syncthreads();
    if (wid == 0) {
        float t = (lane < 8) ? red[lane] : -1e30f;
        t = warpMax(t);
        if (lane == 0) red[0] = t;
    }
    __syncthreads();
    return red[0];
}

// ---------------- q + bias broadcast ---------------------------------------
__global__ void addbias2_kernel(const float* __restrict__ q,
                                const float* __restrict__ wb,
                                const float* __restrict__ rb,
                                float* __restrict__ qw,
                                float* __restrict__ qr)
{
    int t = blockIdx.x * blockDim.x + threadIdx.x;
    float v = q[t];
    int c = t & (Dm - 1);           // h*64 + d
    qw[t] = v + wb[c];
    qr[t] = v + rb[c];
}

// ---------------- fused rel_shift + mask + scale + softmax (in-place) ------
// score[i][j] = (ac[i][j] + bd_raw[i][S-1+j-i]) * scale  for j <= i, else -inf.
__global__ void softmax_kernel(float* __restrict__ ac, const float* __restrict__ bd)
{
    const long row = blockIdx.x;
    const int  i   = (int)(row & (Sq - 1));
    const long base = row * Sq;

    __shared__ float sbuf[Sq];
    const float scale = 0.125f;     // 1/sqrt(64)
    const int tid = threadIdx.x;

    float lmax = -1e30f;
    for (int j = tid; j < Sq; j += blockDim.x) {
        float s = -1e30f;
        if (j <= i)
            s = (ac[base + j] + bd[base + (Sq - 1 + j - i)]) * scale;
        sbuf[j] = s;
        lmax = fmaxf(lmax, s);
    }
    float rmax = blockMax(lmax);

    float lsum = 0.f;
    for (int j = tid; j < Sq; j += blockDim.x) {
        float e = (j <= i) ? __expf(sbuf[j] - rmax) : 0.f;
        sbuf[j] = e;
        lsum += e;
    }
    float rsum = blockSum(lsum);
    float inv = 1.f / rsum;

    for (int j = tid; j < Sq; j += blockDim.x)
        ac[base + j] = sbuf[j] * inv;
}

// ---------------- fused residual + LayerNorm --------------------------------
__global__ void ln_kernel(const float* __restrict__ a, const float* __restrict__ b,
                          const float* __restrict__ gam, const float* __restrict__ bet,
                          float* __restrict__ out)
{
    const long row = blockIdx.x;
    const long base = row * Dm;
    __shared__ float sbuf[Dm];
    const int tid = threadIdx.x;

    float ls = 0.f;
    for (int j = tid; j < Dm; j += blockDim.x) {
        float x = a[base + j] + b[base + j];
        sbuf[j] = x;
        ls += x;
    }
    float mu = blockSum(ls) * (1.f / Dm);

    float lv = 0.f;
    for (int j = tid; j < Dm; j += blockDim.x) {
        float d = sbuf[j] - mu;
        lv += d * d;
    }
    float var = blockSum(lv) * (1.f / Dm);
    float inv = rsqrtf(var + EPS);

    for (int j = tid; j < Dm; j += blockDim.x)
        out[base + j] = (sbuf[j] - mu) * inv * gam[j] + bet[j];
}

// ---------------- launch ----------------------------------------------------
extern "C" void kernel_launch(void* const* d_in, const int* in_sizes, int n_in,
                              void* d_out, int out_size)
{
    const float* w      = (const float*)d_in[0];
    const float* r      = (const float*)d_in[1];
    const float* w_bias = (const float*)d_in[2];
    const float* r_bias = (const float*)d_in[3];
    const float* Wq     = (const float*)d_in[4];
    const float* Wk     = (const float*)d_in[5];
    const float* Wv     = (const float*)d_in[6];
    const float* Wr     = (const float*)d_in[7];
    const float* Wo     = (const float*)d_in[8];
    const float* ln1g   = (const float*)d_in[9];
    const float* ln1b   = (const float*)d_in[10];
    const float* W1     = (const float*)d_in[11];
    const float* b1     = (const float*)d_in[12];
    const float* W2     = (const float*)d_in[13];
    const float* b2     = (const float*)d_in[14];
    const float* ln2g   = (const float*)d_in[15];
    const float* ln2b   = (const float*)d_in[16];
    float* out = (float*)d_out;

    float *q, *k, *v, *rr, *qw, *qr, *ac, *bd, *av, *ao, *x, *h, *f;
    cudaGetSymbolAddress((void**)&q,  g_q);
    cudaGetSymbolAddress((void**)&k,  g_k);
    cudaGetSymbolAddress((void**)&v,  g_v);
    cudaGetSymbolAddress((void**)&rr, g_r);
    cudaGetSymbolAddress((void**)&qw, g_qw);
    cudaGetSymbolAddress((void**)&qr, g_qr);
    cudaGetSymbolAddress((void**)&ac, g_ac);
    cudaGetSymbolAddress((void**)&bd, g_bd);
    cudaGetSymbolAddress((void**)&av, g_av);
    cudaGetSymbolAddress((void**)&ao, g_ao);
    cudaGetSymbolAddress((void**)&x,  g_x);
    cudaGetSymbolAddress((void**)&h,  g_h);
    cudaGetSymbolAddress((void**)&f,  g_f);

    const int M = Bq * Sq;                     // 4096

    // Projections: [4096,1024] @ [1024,1024]
    dim3 gp(Dm / 128, M / 128, 1);             // (8, 32)
    tgemm<128,false,false,false><<<gp, 256>>>(w,  Wq, q,  nullptr, M, Dm, Dm, Dm, Dm, Dm, 0,0,0,0,0,0,1);
    tgemm<128,false,false,false><<<gp, 256>>>(w,  Wk, k,  nullptr, M, Dm, Dm, Dm, Dm, Dm, 0,0,0,0,0,0,1);
    tgemm<128,false,false,false><<<gp, 256>>>(w,  Wv, v,  nullptr, M, Dm, Dm, Dm, Dm, Dm, 0,0,0,0,0,0,1);
    tgemm<128,false,false,false><<<gp, 256>>>(r,  Wr, rr, nullptr, M, Dm, Dm, Dm, Dm, Dm, 0,0,0,0,0,0,1);

    // q + w_bias / q + r_bias
    addbias2_kernel<<<(Bq*Sq*Dm)/256, 256>>>(q, w_bias, r_bias, qw, qr);

    // Batched NT attention scores: per (b,h): [1024,64] @ [1024,64]^T
    dim3 ga(Sq / 128, Sq / 128, Bq * NHh);     // (8, 8, 64)
    tgemm<128,true,false,false><<<ga, 256>>>(qw, k, ac, nullptr,
        Sq, Sq, DHh, Dm, Dm, Sq,
        (long)Sq*Dm, 64, (long)Sq*Dm, 64, (long)NHh*Sq*Sq, (long)Sq*Sq, NHh);
    tgemm<128,true,false,false><<<ga, 256>>>(qr, rr, bd, nullptr,
        Sq, Sq, DHh, Dm, Dm, Sq,
        (long)Sq*Dm, 64, (long)Sq*Dm, 64, (long)NHh*Sq*Sq, (long)Sq*Sq, NHh);

    // rel_shift + causal mask + scale + softmax (probs written into ac)
    softmax_kernel<<<Bq * NHh * Sq, 256>>>(ac, bd);

    // attn_vec = prob @ v  (batched NN, N=64)
    dim3 gv(1, Sq / 128, Bq * NHh);            // (1, 8, 64)
    tgemm<64,false,false,false><<<gv, 128>>>(ac, v, av, nullptr,
        Sq, DHh, Sq, Sq, Dm, Dm,
        (long)NHh*Sq*Sq, (long)Sq*Sq, (long)Sq*Dm, 64, (long)Sq*Dm, 64, NHh);

    // attn_out = attn_vec @ Wo
    tgemm<128,false,false,false><<<gp, 256>>>(av, Wo, ao, nullptr, M, Dm, Dm, Dm, Dm, Dm, 0,0,0,0,0,0,1);

    // x = LN(w + attn_out)
    ln_kernel<<<M, 256>>>(w, ao, ln1g, ln1b, x);

    // FFN: h = relu(x @ W1 + b1); f = h @ W2 + b2
    dim3 gf1(DIf / 128, M / 128, 1);           // (32, 32)
    tgemm<128,false,true, true ><<<gf1, 256>>>(x, W1, h, b1, M, DIf, Dm,  Dm,  DIf, DIf, 0,0,0,0,0,0,1);
    tgemm<128,false,false,true ><<<gp,  256>>>(h, W2, f, b2, M, Dm,  DIf, DIf, Dm,  Dm,  0,0,0,0,0,0,1);

    // out = LN(x + f)
    ln_kernel<<<M, 256>>>(x, f, ln2g, ln2b, out);
}

// round 5
// speedup vs baseline: 2.8078x; 2.3887x over previous
#include <cuda_runtime.h>
#include <math.h>

// Problem constants
#define Bq  4
#define Sq  1024
#define Dm  1024
#define NHh 16
#define DHh 64
#define DIf 4096
#define EPS 1e-5f

// ---------------- scratch (static device globals; no allocations) ----------
__device__ float g_q [Bq*Sq*Dm];
__device__ float g_k [Bq*Sq*Dm];
__device__ float g_v [Bq*Sq*Dm];
__device__ float g_r [Bq*Sq*Dm];
__device__ float g_qw[Bq*Sq*Dm];
__device__ float g_qr[Bq*Sq*Dm];
__device__ float g_ac[(size_t)Bq*NHh*Sq*Sq];   // scores -> probs (in place)
__device__ float g_bd[(size_t)Bq*NHh*Sq*Sq];   // raw bd (pre rel_shift)
__device__ float g_av[Bq*Sq*Dm];
__device__ float g_ao[Bq*Sq*Dm];
__device__ float g_x [Bq*Sq*Dm];
__device__ float g_h [Bq*Sq*DIf];
__device__ float g_f [Bq*Sq*Dm];

// ---------------- tf32 / cp.async helpers -----------------------------------
__device__ __forceinline__ unsigned f2tf(float v) {
    unsigned r;
    asm("cvt.rna.tf32.f32 %0, %1;" : "=r"(r) : "f"(v));
    return r;
}

__device__ __forceinline__ void mma_tf32(float* d, const uint4& a, const uint2& b) {
    asm volatile(
        "mma.sync.aligned.m16n8k8.row.col.f32.tf32.tf32.f32 "
        "{%0,%1,%2,%3}, {%4,%5,%6,%7}, {%8,%9}, {%0,%1,%2,%3};"
        : "+f"(d[0]), "+f"(d[1]), "+f"(d[2]), "+f"(d[3])
        : "r"(a.x), "r"(a.y), "r"(a.z), "r"(a.w), "r"(b.x), "r"(b.y));
}

__device__ __forceinline__ void cp16(unsigned s, const void* g) {
    asm volatile("cp.async.cg.shared.global [%0], [%1], 16;" :: "r"(s), "l"(g));
}
#define CP_COMMIT() asm volatile("cp.async.commit_group;")
#define CP_WAIT0()  asm volatile("cp.async.wait_group 0;")

// ---------------- TF32 tensor-core GEMM --------------------------------------
// C[M,N] = A[M,K] @ op(B); op(B) = B[K,N] (TB=false) or B[N,K]^T (TB=true)
// Block 128 x BN, BK=16, 2-stage cp.async pipeline. Warp tile 64x32.
// Threads = 2*BN. BN in {64,128}. Conflict-free smem:
//   A : [128][20] row-major      (frag banks (20r+c)%32 all distinct)
//   B : TB  -> [BN][20] n-major  (same property)
//        !TB -> [16][BN+8] k-major (banks 8k+n distinct)
template<int BN, bool TB, bool RELU, bool HASBIAS>
__global__ void __launch_bounds__(BN*2)
tgemm(const float* __restrict__ A, const float* __restrict__ B,
      float* __restrict__ C, const float* __restrict__ bias,
      int M, int N, int K, int lda, int ldb, int ldc,
      long offA1, long offA2, long offB1, long offB2,
      long offC1, long offC2, int nh)
{
    constexpr int BK = 16;
    constexpr int THREADS = BN * 2;
    constexpr int A_IT = 512 / THREADS;            // float4 of A per thread
    constexpr int B_IT = (4 * BN) / THREADS;       // float4 of B per thread
    constexpr int AS = 20;                          // A row stride (words)
    constexpr int BSN = BN + 8;                     // !TB row stride
    constexpr int BSM = TB ? (BN * AS) : (BK * BSN);

    __shared__ __align__(16) float As[2][128 * AS];
    __shared__ __align__(16) float Bs[2][BSM];

    const int g = blockIdx.z;
    const float* Ab = A + (long)(g / nh) * offA1 + (long)(g % nh) * offA2;
    const float* Bb = B + (long)(g / nh) * offB1 + (long)(g % nh) * offB2;
    float*       Cb = C + (long)(g / nh) * offC1 + (long)(g % nh) * offC2;

    const int m0 = blockIdx.y * 128;
    const int n0 = blockIdx.x * BN;
    const int tid  = threadIdx.x;
    const int lane = tid & 31;
    const int wid  = tid >> 5;
    const int warp_m = wid & 1;
    const int warp_n = wid >> 1;

    float acc[4][4][4];
    #pragma unroll
    for (int i = 0; i < 4; i++)
        #pragma unroll
        for (int j = 0; j < 4; j++)
            #pragma unroll
            for (int l = 0; l < 4; l++) acc[i][j][l] = 0.f;

    const int ntiles = K / BK;

    unsigned aBase[2] = { (unsigned)__cvta_generic_to_shared(&As[0][0]),
                          (unsigned)__cvta_generic_to_shared(&As[1][0]) };
    unsigned bBase[2] = { (unsigned)__cvta_generic_to_shared(&Bs[0][0]),
                          (unsigned)__cvta_generic_to_shared(&Bs[1][0]) };

    auto issue = [&](int t, int buf) {
        const int k0 = t * BK;
        #pragma unroll
        for (int i = 0; i < A_IT; i++) {
            int e = tid + i * THREADS;
            int row = e >> 2, kk = (e & 3) << 2;
            cp16(aBase[buf] + (unsigned)(row * AS + kk) * 4,
                 &Ab[(long)(m0 + row) * lda + k0 + kk]);
        }
        #pragma unroll
        for (int i = 0; i < B_IT; i++) {
            int e = tid + i * THREADS;
            if (TB) {
                int n = e >> 2, kk = (e & 3) << 2;
                cp16(bBase[buf] + (unsigned)(n * AS + kk) * 4,
                     &Bb[(long)(n0 + n) * ldb + k0 + kk]);
            } else {
                int kk = e / (BN / 4), n = (e % (BN / 4)) * 4;
                cp16(bBase[buf] + (unsigned)(kk * BSN + n) * 4,
                     &Bb[(long)(k0 + kk) * ldb + n0 + n]);
            }
        }
    };

    auto compute = [&](int buf) {
        const float* Aw = As[buf];
        const float* Bw = Bs[buf];
        const int r = lane >> 2, c = lane & 3;
        #pragma unroll
        for (int ks = 0; ks < 2; ks++) {
            uint4 af[4];
            #pragma unroll
            for (int mt = 0; mt < 4; mt++) {
                const float* p = &Aw[(warp_m * 64 + mt * 16 + r) * AS + ks * 8 + c];
                af[mt].x = f2tf(p[0]);
                af[mt].y = f2tf(p[8 * AS]);
                af[mt].z = f2tf(p[4]);
                af[mt].w = f2tf(p[8 * AS + 4]);
            }
            uint2 bf[4];
            #pragma unroll
            for (int nt = 0; nt < 4; nt++) {
                int n = warp_n * 32 + nt * 8 + r;
                if (TB) {
                    const float* p = &Bw[n * AS + ks * 8 + c];
                    bf[nt].x = f2tf(p[0]);
                    bf[nt].y = f2tf(p[4]);
                } else {
                    const float* p = &Bw[(ks * 8 + c) * BSN + n];
                    bf[nt].x = f2tf(p[0]);
                    bf[nt].y = f2tf(p[4 * BSN]);
                }
            }
            #pragma unroll
            for (int mt = 0; mt < 4; mt++)
                #pragma unroll
                for (int nt = 0; nt < 4; nt++)
                    mma_tf32(acc[mt][nt], af[mt], bf[nt]);
        }
    };

    // 2-stage pipeline: load(t+1) overlaps compute(t)
    issue(0, 0); CP_COMMIT();
    for (int t = 0; t < ntiles; t++) {
        CP_WAIT0();
        __syncthreads();
        if (t + 1 < ntiles) { issue(t + 1, (t + 1) & 1); CP_COMMIT(); }
        compute(t & 1);
        __syncthreads();
    }

    // ---- epilogue ----
    #pragma unroll
    for (int mt = 0; mt < 4; mt++) {
        int rbase = m0 + warp_m * 64 + mt * 16 + (lane >> 2);
        #pragma unroll
        for (int nt = 0; nt < 4; nt++) {
            int cbase = n0 + warp_n * 32 + nt * 8 + (lane & 3) * 2;
            float* d = acc[mt][nt];
            float b0 = 0.f, b1 = 0.f;
            if (HASBIAS) { b0 = bias[cbase]; b1 = bias[cbase + 1]; }
            float v0 = d[0] + b0, v1 = d[1] + b1;
            float v2 = d[2] + b0, v3 = d[3] + b1;
            if (RELU) {
                v0 = fmaxf(v0, 0.f); v1 = fmaxf(v1, 0.f);
                v2 = fmaxf(v2, 0.f); v3 = fmaxf(v3, 0.f);
            }
            *(float2*)&Cb[(long)rbase * ldc + cbase]       = make_float2(v0, v1);
            *(float2*)&Cb[(long)(rbase + 8) * ldc + cbase] = make_float2(v2, v3);
        }
    }
}

// ---------------- reductions ----------------------------------------------
__device__ __forceinline__ float warpSum(float v) {
    #pragma unroll
    for (int o = 16; o > 0; o >>= 1) v += __shfl_xor_sync(0xffffffffu, v, o);
    return v;
}
__device__ __forceinline__ float warpMax(float v) {
    #pragma unroll
    for (int o = 16; o > 0; o >>= 1) v = fmaxf(v, __shfl_xor_sync(0xffffffffu, v, o));
    return v;
}
__device__ float blockSum(float v) {
    __shared__ float red[8];
    __syncthreads();
    int lane = threadIdx.x & 31, wid = threadIdx.x >> 5;
    v = warpSum(v);
    if (lane == 0) red[wid] = v;
    __syncthreads();
    if (wid == 0) {
        float t = (lane < 8) ? red[lane] : 0.f;
        t = warpSum(t);
        if (lane == 0) red[0] = t;
    }
    __syncthreads();
    return red[0];
}
__device__ float blockMax(float v) {
    __shared__ float red[8];
    __syncthreads();
    int lane = threadIdx.x & 31, wid = threadIdx.x >> 5;
    v = warpMax(v);
    if (lane == 0) red[wid] = v;
    __syncthreads();
    if (wid == 0) {
        float t = (lane < 8) ? red[lane] : -1e30f;
        t = warpMax(t);
        if (lane == 0) red[0] = t;
    }
    __syncthreads();
    return red[0];
}

// ---------------- q + bias broadcast ---------------------------------------
__global__ void addbias2_kernel(const float* __restrict__ q,
                                const float* __restrict__ wb,
                                const float* __restrict__ rb,
                                float* __restrict__ qw,
                                float* __restrict__ qr)
{
    int t = blockIdx.x * blockDim.x + threadIdx.x;
    float v = q[t];
    int c = t & (Dm - 1);           // h*64 + d
    qw[t] = v + wb[c];
    qr[t] = v + rb[c];
}

// ---------------- fused rel_shift + mask + scale + softmax (in-place) ------
// score[i][j] = (ac[i][j] + bd_raw[i][S-1+j-i]) * scale  for j <= i, else -inf.
__global__ void softmax_kernel(float* __restrict__ ac, const float* __restrict__ bd)
{
    const long row = blockIdx.x;
    const int  i   = (int)(row & (Sq - 1));
    const long base = row * Sq;

    __shared__ float sbuf[Sq];
    const float scale = 0.125f;     // 1/sqrt(64)
    const int tid = threadIdx.x;

    float lmax = -1e30f;
    for (int j = tid; j < Sq; j += blockDim.x) {
        float s = -1e30f;
        if (j <= i)
            s = (ac[base + j] + bd[base + (Sq - 1 + j - i)]) * scale;
        sbuf[j] = s;
        lmax = fmaxf(lmax, s);
    }
    float rmax = blockMax(lmax);

    float lsum = 0.f;
    for (int j = tid; j < Sq; j += blockDim.x) {
        float e = (j <= i) ? __expf(sbuf[j] - rmax) : 0.f;
        sbuf[j] = e;
        lsum += e;
    }
    float rsum = blockSum(lsum);
    float inv = 1.f / rsum;

    for (int j = tid; j < Sq; j += blockDim.x)
        ac[base + j] = sbuf[j] * inv;
}

// ---------------- fused residual + LayerNorm --------------------------------
__global__ void ln_kernel(const float* __restrict__ a, const float* __restrict__ b,
                          const float* __restrict__ gam, const float* __restrict__ bet,
                          float* __restrict__ out)
{
    const long row = blockIdx.x;
    const long base = row * Dm;
    __shared__ float sbuf[Dm];
    const int tid = threadIdx.x;

    float ls = 0.f;
    for (int j = tid; j < Dm; j += blockDim.x) {
        float x = a[base + j] + b[base + j];
        sbuf[j] = x;
        ls += x;
    }
    float mu = blockSum(ls) * (1.f / Dm);

    float lv = 0.f;
    for (int j = tid; j < Dm; j += blockDim.x) {
        float d = sbuf[j] - mu;
        lv += d * d;
    }
    float var = blockSum(lv) * (1.f / Dm);
    float inv = rsqrtf(var + EPS);

    for (int j = tid; j < Dm; j += blockDim.x)
        out[base + j] = (sbuf[j] - mu) * inv * gam[j] + bet[j];
}

// ---------------- launch ----------------------------------------------------
extern "C" void kernel_launch(void* const* d_in, const int* in_sizes, int n_in,
                              void* d_out, int out_size)
{
    const float* w      = (const float*)d_in[0];
    const float* r      = (const float*)d_in[1];
    const float* w_bias = (const float*)d_in[2];
    const float* r_bias = (const float*)d_in[3];
    const float* Wq     = (const float*)d_in[4];
    const float* Wk     = (const float*)d_in[5];
    const float* Wv     = (const float*)d_in[6];
    const float* Wr     = (const float*)d_in[7];
    const float* Wo     = (const float*)d_in[8];
    const float* ln1g   = (const float*)d_in[9];
    const float* ln1b   = (const float*)d_in[10];
    const float* W1     = (const float*)d_in[11];
    const float* b1     = (const float*)d_in[12];
    const float* W2     = (const float*)d_in[13];
    const float* b2     = (const float*)d_in[14];
    const float* ln2g   = (const float*)d_in[15];
    const float* ln2b   = (const float*)d_in[16];
    float* out = (float*)d_out;

    float *q, *k, *v, *rr, *qw, *qr, *ac, *bd, *av, *ao, *x, *h, *f;
    cudaGetSymbolAddress((void**)&q,  g_q);
    cudaGetSymbolAddress((void**)&k,  g_k);
    cudaGetSymbolAddress((void**)&v,  g_v);
    cudaGetSymbolAddress((void**)&rr, g_r);
    cudaGetSymbolAddress((void**)&qw, g_qw);
    cudaGetSymbolAddress((void**)&qr, g_qr);
    cudaGetSymbolAddress((void**)&ac, g_ac);
    cudaGetSymbolAddress((void**)&bd, g_bd);
    cudaGetSymbolAddress((void**)&av, g_av);
    cudaGetSymbolAddress((void**)&ao, g_ao);
    cudaGetSymbolAddress((void**)&x,  g_x);
    cudaGetSymbolAddress((void**)&h,  g_h);
    cudaGetSymbolAddress((void**)&f,  g_f);

    const int M = Bq * Sq;                     // 4096

    // Projections: [4096,1024] @ [1024,1024]
    dim3 gp(Dm / 128, M / 128, 1);             // (8, 32)
    tgemm<128,false,false,false><<<gp, 256>>>(w,  Wq, q,  nullptr, M, Dm, Dm, Dm, Dm, Dm, 0,0,0,0,0,0,1);
    tgemm<128,false,false,false><<<gp, 256>>>(w,  Wk, k,  nullptr, M, Dm, Dm, Dm, Dm, Dm, 0,0,0,0,0,0,1);
    tgemm<128,false,false,false><<<gp, 256>>>(w,  Wv, v,  nullptr, M, Dm, Dm, Dm, Dm, Dm, 0,0,0,0,0,0,1);
    tgemm<128,false,false,false><<<gp, 256>>>(r,  Wr, rr, nullptr, M, Dm, Dm, Dm, Dm, Dm, 0,0,0,0,0,0,1);

    // q + w_bias / q + r_bias
    addbias2_kernel<<<(Bq*Sq*Dm)/256, 256>>>(q, w_bias, r_bias, qw, qr);

    // Batched NT attention scores: per (b,h): [1024,64] @ [1024,64]^T
    dim3 ga(Sq / 128, Sq / 128, Bq * NHh);     // (8, 8, 64)
    tgemm<128,true,false,false><<<ga, 256>>>(qw, k, ac, nullptr,
        Sq, Sq, DHh, Dm, Dm, Sq,
        (long)Sq*Dm, 64, (long)Sq*Dm, 64, (long)NHh*Sq*Sq, (long)Sq*Sq, NHh);
    tgemm<128,true,false,false><<<ga, 256>>>(qr, rr, bd, nullptr,
        Sq, Sq, DHh, Dm, Dm, Sq,
        (long)Sq*Dm, 64, (long)Sq*Dm, 64, (long)NHh*Sq*Sq, (long)Sq*Sq, NHh);

    // rel_shift + causal mask + scale + softmax (probs written into ac)
    softmax_kernel<<<Bq * NHh * Sq, 256>>>(ac, bd);

    // attn_vec = prob @ v  (batched NN, N=64)
    dim3 gv(1, Sq / 128, Bq * NHh);            // (1, 8, 64)
    tgemm<64,false,false,false><<<gv, 128>>>(ac, v, av, nullptr,
        Sq, DHh, Sq, Sq, Dm, Dm,
        (long)NHh*Sq*Sq, (long)Sq*Sq, (long)Sq*Dm, 64, (long)Sq*Dm, 64, NHh);

    // attn_out = attn_vec @ Wo
    tgemm<128,false,false,false><<<gp, 256>>>(av, Wo, ao, nullptr, M, Dm, Dm, Dm, Dm, Dm, 0,0,0,0,0,0,1);

    // x = LN(w + attn_out)
    ln_kernel<<<M, 256>>>(w, ao, ln1g, ln1b, x);

    // FFN: h = relu(x @ W1 + b1); f = h @ W2 + b2
    dim3 gf1(DIf / 128, M / 128, 1);           // (32, 32)
    tgemm<128,false,true, true ><<<gf1, 256>>>(x, W1, h, b1, M, DIf, Dm,  Dm,  DIf, DIf, 0,0,0,0,0,0,1);
    tgemm<128,false,false,true ><<<gp,  256>>>(h, W2, f, b2, M, Dm,  DIf, DIf, Dm,  Dm,  0,0,0,0,0,0,1);

    // out = LN(x + f)
    ln_kernel<<<M, 256>>>(x, f, ln2g, ln2b, out);
}

// round 6
// speedup vs baseline: 3.0654x; 1.0917x over previous
#include <cuda_runtime.h>
#include <math.h>

// Problem constants
#define Bq  4
#define Sq  1024
#define Dm  1024
#define NHh 16
#define DHh 64
#define DIf 4096
#define EPS 1e-5f

// ---------------- scratch (static device globals; no allocations) ----------
__device__ float g_q [Bq*Sq*Dm];
__device__ float g_k [Bq*Sq*Dm];
__device__ float g_v [Bq*Sq*Dm];
__device__ float g_r [Bq*Sq*Dm];
__device__ float g_qw[Bq*Sq*Dm];
__device__ float g_qr[Bq*Sq*Dm];
__device__ float g_ac[(size_t)Bq*NHh*Sq*Sq];   // scores -> probs (in place)
__device__ float g_bd[(size_t)Bq*NHh*Sq*Sq];   // raw bd (pre rel_shift)
__device__ float g_av[Bq*Sq*Dm];
__device__ float g_ao[Bq*Sq*Dm];
__device__ float g_x [Bq*Sq*Dm];
__device__ float g_xr[Bq*Sq*Dm];
__device__ float g_h [Bq*Sq*DIf];
__device__ float g_f [Bq*Sq*Dm];
// tf32-rounded copies of inputs
__device__ float g_wr [Bq*Sq*Dm];
__device__ float g_rr2[Bq*Sq*Dm];
__device__ float g_Wqr[Dm*Dm];
__device__ float g_Wkr[Dm*Dm];
__device__ float g_Wvr[Dm*Dm];
__device__ float g_Wrr[Dm*Dm];
__device__ float g_Wor[Dm*Dm];
__device__ float g_W1r[Dm*DIf];
__device__ float g_W2r[DIf*Dm];

// ---------------- tf32 / mma / ldmatrix / cp.async helpers ------------------
__device__ __forceinline__ unsigned f2tf(float v) {
    unsigned r;
    asm("cvt.rna.tf32.f32 %0, %1;" : "=r"(r) : "f"(v));
    return r;
}
__device__ __forceinline__ float roundtf(float v) { return __uint_as_float(f2tf(v)); }

__device__ __forceinline__ void mma_tf32(float* d, const uint4& a, const uint2& b) {
    asm volatile(
        "mma.sync.aligned.m16n8k8.row.col.f32.tf32.tf32.f32 "
        "{%0,%1,%2,%3}, {%4,%5,%6,%7}, {%8,%9}, {%0,%1,%2,%3};"
        : "+f"(d[0]), "+f"(d[1]), "+f"(d[2]), "+f"(d[3])
        : "r"(a.x), "r"(a.y), "r"(a.z), "r"(a.w), "r"(b.x), "r"(b.y));
}

__device__ __forceinline__ uint4 ldsm4(unsigned addr) {
    uint4 d;
    asm volatile("ldmatrix.sync.aligned.m8n8.x4.shared.b16 {%0,%1,%2,%3}, [%4];"
                 : "=r"(d.x), "=r"(d.y), "=r"(d.z), "=r"(d.w) : "r"(addr));
    return d;
}

__device__ __forceinline__ void cp16(unsigned s, const void* g) {
    asm volatile("cp.async.cg.shared.global [%0], [%1], 16;" :: "r"(s), "l"(g));
}
#define CP_COMMIT() asm volatile("cp.async.commit_group;")
#define CP_WAIT1()  asm volatile("cp.async.wait_group 1;")

// ---------------- TF32 tensor-core GEMM core ---------------------------------
// C[M,N] = A[M,K] @ op(B). Block 128 x BN, BK=16, 3-stage cp.async pipeline.
// Warp tile 64x32 (4x4 m16n8k8). Fragments via ldmatrix (A always; B if TB).
// Inputs must be tf32-pre-rounded in gmem (MMA truncation is then exact-rna).
template<int BN, bool TB, bool RELU, bool HASBIAS, bool CVT>
__device__ __forceinline__ void gemm_core(
    const float* __restrict__ Ab, const float* __restrict__ Bb,
    float* __restrict__ Cb, const float* __restrict__ bias,
    int K, int lda, int ldb, int ldc, float* sm)
{
    constexpr int BK = 16;
    constexpr int THREADS = BN * 2;
    constexpr int AS = 20;                       // A/B(TB) row stride (words)
    constexpr int BSN = BN + 8;                  // !TB row stride
    constexpr int A_W = 128 * AS;
    constexpr int B_W = TB ? BN * AS : BK * BSN;
    constexpr int A_IT = 512 / THREADS;
    constexpr int B_IT = (4 * BN) / THREADS;

    float* As = sm;
    float* Bs = sm + 3 * A_W;

    const int m0 = blockIdx.y * 128;
    const int n0 = blockIdx.x * BN;
    const int tid  = threadIdx.x;
    const int lane = tid & 31;
    const int wid  = tid >> 5;
    const int warp_m = wid & 1;
    const int warp_n = wid >> 1;

    float acc[4][4][4];
    #pragma unroll
    for (int i = 0; i < 4; i++)
        #pragma unroll
        for (int j = 0; j < 4; j++)
            #pragma unroll
            for (int l = 0; l < 4; l++) acc[i][j][l] = 0.f;

    const unsigned aB = (unsigned)__cvta_generic_to_shared(As);
    const unsigned bB = (unsigned)__cvta_generic_to_shared(Bs);
    const int ntiles = K / BK;

    auto issue = [&](int t, int s) {
        const int k0 = t * BK;
        const unsigned ab = aB + (unsigned)(s * A_W) * 4;
        const unsigned bb = bB + (unsigned)(s * B_W) * 4;
        #pragma unroll
        for (int i = 0; i < A_IT; i++) {
            int e = tid + i * THREADS;
            int row = e >> 2, kk = (e & 3) << 2;
            cp16(ab + (unsigned)(row * AS + kk) * 4,
                 &Ab[(long)(m0 + row) * lda + k0 + kk]);
        }
        #pragma unroll
        for (int i = 0; i < B_IT; i++) {
            int e = tid + i * THREADS;
            if (TB) {
                int n = e >> 2, kk = (e & 3) << 2;
                cp16(bb + (unsigned)(n * AS + kk) * 4,
                     &Bb[(long)(n0 + n) * ldb + k0 + kk]);
            } else {
                int kk = e / (BN / 4), n = (e % (BN / 4)) * 4;
                cp16(bb + (unsigned)(kk * BSN + n) * 4,
                     &Bb[(long)(k0 + kk) * ldb + n0 + n]);
            }
        }
    };

    auto compute = [&](int s) {
        const unsigned ab = aB + (unsigned)(s * A_W) * 4;
        const unsigned bb = bB + (unsigned)(s * B_W) * 4;
        const float* Bw = Bs + s * B_W;
        const int q = lane >> 3, ri = lane & 7;
        #pragma unroll
        for (int ks = 0; ks < 2; ks++) {
            uint4 af[4];
            #pragma unroll
            for (int mt = 0; mt < 4; mt++) {
                int row = warp_m * 64 + mt * 16 + (q & 1) * 8 + ri;
                int col = ks * 8 + (q >> 1) * 4;
                af[mt] = ldsm4(ab + (unsigned)(row * AS + col) * 4);
            }
            uint2 bf[4];
            if (TB) {
                #pragma unroll
                for (int p = 0; p < 2; p++) {
                    int n = warp_n * 32 + p * 16 + (q >> 1) * 8 + ri;
                    int col = ks * 8 + (q & 1) * 4;
                    uint4 d = ldsm4(bb + (unsigned)(n * AS + col) * 4);
                    bf[2*p  ].x = d.x; bf[2*p  ].y = d.y;
                    bf[2*p+1].x = d.z; bf[2*p+1].y = d.w;
                }
            } else {
                const int r = lane >> 2, c = lane & 3;
                #pragma unroll
                for (int nt = 0; nt < 4; nt++) {
                    int n = warp_n * 32 + nt * 8 + r;
                    const float* p = &Bw[(ks * 8 + c) * BSN + n];
                    bf[nt].x = __float_as_uint(p[0]);
                    bf[nt].y = __float_as_uint(p[4 * BSN]);
                }
            }
            #pragma unroll
            for (int mt = 0; mt < 4; mt++)
                #pragma unroll
                for (int nt = 0; nt < 4; nt++)
                    mma_tf32(acc[mt][nt], af[mt], bf[nt]);
        }
    };

    // 3-stage pipeline; one commit per iteration (possibly empty) keeps
    // wait_group accounting exact.
    issue(0, 0); CP_COMMIT();
    if (ntiles > 1) issue(1, 1);
    CP_COMMIT();
    for (int t = 0; t < ntiles; t++) {
        CP_WAIT1();
        __syncthreads();
        if (t + 2 < ntiles) issue(t + 2, (t + 2) % 3);
        CP_COMMIT();
        compute(t % 3);
    }

    // ---- epilogue ----
    #pragma unroll
    for (int mt = 0; mt < 4; mt++) {
        int rbase = m0 + warp_m * 64 + mt * 16 + (lane >> 2);
        #pragma unroll
        for (int nt = 0; nt < 4; nt++) {
            int cbase = n0 + warp_n * 32 + nt * 8 + (lane & 3) * 2;
            float* d = acc[mt][nt];
            float b0 = 0.f, b1 = 0.f;
            if (HASBIAS) { b0 = bias[cbase]; b1 = bias[cbase + 1]; }
            float v0 = d[0] + b0, v1 = d[1] + b1;
            float v2 = d[2] + b0, v3 = d[3] + b1;
            if (RELU) {
                v0 = fmaxf(v0, 0.f); v1 = fmaxf(v1, 0.f);
                v2 = fmaxf(v2, 0.f); v3 = fmaxf(v3, 0.f);
            }
            if (CVT) {
                v0 = roundtf(v0); v1 = roundtf(v1);
                v2 = roundtf(v2); v3 = roundtf(v3);
            }
            *(float2*)&Cb[(long)rbase * ldc + cbase]       = make_float2(v0, v1);
            *(float2*)&Cb[(long)(rbase + 8) * ldc + cbase] = make_float2(v2, v3);
        }
    }
}

// ---------------- wrapper with pointer-select batching -----------------------
struct Sel4 {
    const float* A[4]; const float* B[4]; float* C[4]; const float* bias[4];
};

template<int BN, bool TB, bool RELU, bool HASBIAS, bool CVT>
__global__ void __launch_bounds__(BN*2)
tg(Sel4 p, int K, int lda, int ldb, int ldc,
   long offA1, long offA2, long offB1, long offB2, long offC1, long offC2,
   int nh, int bps)
{
    extern __shared__ float sm[];
    const int z = blockIdx.z;
    const int sel = z / bps, b = z - sel * bps;
    const float* Ab = p.A[sel] + (long)(b / nh) * offA1 + (long)(b % nh) * offA2;
    const float* Bb = p.B[sel] + (long)(b / nh) * offB1 + (long)(b % nh) * offB2;
    float*       Cb = p.C[sel] + (long)(b / nh) * offC1 + (long)(b % nh) * offC2;
    gemm_core<BN, TB, RELU, HASBIAS, CVT>(Ab, Bb, Cb, p.bias[sel],
                                          K, lda, ldb, ldc, sm);
}

template<int BN, bool TB, bool RELU, bool HASBIAS, bool CVT>
static void launch_tg(dim3 grid, const Sel4& p, int K, int lda, int ldb, int ldc,
                      long oA1, long oA2, long oB1, long oB2, long oC1, long oC2,
                      int nh, int bps)
{
    constexpr int smem = 3 * (128 * 20 + (TB ? BN * 20 : 16 * (BN + 8))) * 4;
    cudaFuncSetAttribute(tg<BN, TB, RELU, HASBIAS, CVT>,
                         cudaFuncAttributeMaxDynamicSharedMemorySize, smem);
    tg<BN, TB, RELU, HASBIAS, CVT><<<grid, BN * 2, smem>>>(
        p, K, lda, ldb, ldc, oA1, oA2, oB1, oB2, oC1, oC2, nh, bps);
}

// ---------------- input tf32 pre-round pass ---------------------------------
struct RSeg { const float4* s; float4* d; int n4; };
struct R9   { RSeg seg[9]; };

__global__ void round9_kernel(R9 r) {
    RSeg sg = r.seg[blockIdx.y];
    for (int i = blockIdx.x * blockDim.x + threadIdx.x; i < sg.n4;
         i += gridDim.x * blockDim.x) {
        float4 v = sg.s[i];
        v.x = roundtf(v.x); v.y = roundtf(v.y);
        v.z = roundtf(v.z); v.w = roundtf(v.w);
        sg.d[i] = v;
    }
}

// ---------------- reductions ----------------------------------------------
__device__ __forceinline__ float warpSum(float v) {
    #pragma unroll
    for (int o = 16; o > 0; o >>= 1) v += __shfl_xor_sync(0xffffffffu, v, o);
    return v;
}
__device__ __forceinline__ float warpMax(float v) {
    #pragma unroll
    for (int o = 16; o > 0; o >>= 1) v = fmaxf(v, __shfl_xor_sync(0xffffffffu, v, o));
    return v;
}
__device__ float blockSum(float v) {
    __shared__ float red[8];
    __syncthreads();
    int lane = threadIdx.x & 31, wid = threadIdx.x >> 5;
    v = warpSum(v);
    if (lane == 0) red[wid] = v;
    __syncthreads();
    if (wid == 0) {
        float t = (lane < 8) ? red[lane] : 0.f;
        t = warpSum(t);
        if (lane == 0) red[0] = t;
    }
    __syncthreads();
    return red[0];
}
__device__ float blockMax(float v) {
    __shared__ float red[8];
    __syncthreads();
    int lane = threadIdx.x & 31, wid = threadIdx.x >> 5;
    v = warpMax(v);
    if (lane == 0) red[wid] = v;
    __syncthreads();
    if (wid == 0) {
        float t = (lane < 8) ? red[lane] : -1e30f;
        t = warpMax(t);
        if (lane == 0) red[0] = t;
    }
    __syncthreads();
    return red[0];
}

// ---------------- q + bias broadcast (tf32-rounded outputs) -----------------
__global__ void addbias2_kernel(const float* __restrict__ q,
                                const float* __restrict__ wb,
                                const float* __restrict__ rb,
                                float* __restrict__ qw,
                                float* __restrict__ qr)
{
    int t = blockIdx.x * blockDim.x + threadIdx.x;
    float v = q[t];
    int c = t & (Dm - 1);           // h*64 + d
    qw[t] = roundtf(v + wb[c]);
    qr[t] = roundtf(v + rb[c]);
}

// ---------------- fused rel_shift + mask + scale + softmax (in-place) ------
__global__ void softmax_kernel(float* __restrict__ ac, const float* __restrict__ bd)
{
    const long row = blockIdx.x;
    const int  i   = (int)(row & (Sq - 1));
    const long base = row * Sq;

    __shared__ float sbuf[Sq];
    const float scale = 0.125f;     // 1/sqrt(64)
    const int tid = threadIdx.x;

    float lmax = -1e30f;
    for (int j = tid; j < Sq; j += blockDim.x) {
        float s = -1e30f;
        if (j <= i)
            s = (ac[base + j] + bd[base + (Sq - 1 + j - i)]) * scale;
        sbuf[j] = s;
        lmax = fmaxf(lmax, s);
    }
    float rmax = blockMax(lmax);

    float lsum = 0.f;
    for (int j = tid; j < Sq; j += blockDim.x) {
        float e = (j <= i) ? __expf(sbuf[j] - rmax) : 0.f;
        sbuf[j] = e;
        lsum += e;
    }
    float rsum = blockSum(lsum);
    float inv = 1.f / rsum;

    for (int j = tid; j < Sq; j += blockDim.x)
        ac[base + j] = roundtf(sbuf[j] * inv);   // probs feed AV GEMM
}

// ---------------- fused residual + LayerNorm (optional tf32 copy) -----------
__global__ void ln_kernel(const float* __restrict__ a, const float* __restrict__ b,
                          const float* __restrict__ gam, const float* __restrict__ bet,
                          float* __restrict__ out, float* __restrict__ out_tf)
{
    const long row = blockIdx.x;
    const long base = row * Dm;
    __shared__ float sbuf[Dm];
    const int tid = threadIdx.x;

    float ls = 0.f;
    for (int j = tid; j < Dm; j += blockDim.x) {
        float x = a[base + j] + b[base + j];
        sbuf[j] = x;
        ls += x;
    }
    float mu = blockSum(ls) * (1.f / Dm);

    float lv = 0.f;
    for (int j = tid; j < Dm; j += blockDim.x) {
        float d = sbuf[j] - mu;
        lv += d * d;
    }
    float var = blockSum(lv) * (1.f / Dm);
    float inv = rsqrtf(var + EPS);

    for (int j = tid; j < Dm; j += blockDim.x) {
        float y = (sbuf[j] - mu) * inv * gam[j] + bet[j];
        out[base + j] = y;
        if (out_tf) out_tf[base + j] = roundtf(y);
    }
}

// ---------------- launch ----------------------------------------------------
extern "C" void kernel_launch(void* const* d_in, const int* in_sizes, int n_in,
                              void* d_out, int out_size)
{
    const float* w      = (const float*)d_in[0];
    const float* r      = (const float*)d_in[1];
    const float* w_bias = (const float*)d_in[2];
    const float* r_bias = (const float*)d_in[3];
    const float* b1     = (const float*)d_in[12];
    const float* b2     = (const float*)d_in[14];
    const float* ln1g   = (const float*)d_in[9];
    const float* ln1b   = (const float*)d_in[10];
    const float* ln2g   = (const float*)d_in[15];
    const float* ln2b   = (const float*)d_in[16];
    float* out = (float*)d_out;

    float *q, *k, *v, *rr, *qw, *qr, *ac, *bd, *av, *ao, *x, *xr, *h, *f;
    float *wr, *rr2, *Wqr, *Wkr, *Wvr, *Wrr, *Wor, *W1r, *W2r;
    cudaGetSymbolAddress((void**)&q,   g_q);
    cudaGetSymbolAddress((void**)&k,   g_k);
    cudaGetSymbolAddress((void**)&v,   g_v);
    cudaGetSymbolAddress((void**)&rr,  g_r);
    cudaGetSymbolAddress((void**)&qw,  g_qw);
    cudaGetSymbolAddress((void**)&qr,  g_qr);
    cudaGetSymbolAddress((void**)&ac,  g_ac);
    cudaGetSymbolAddress((void**)&bd,  g_bd);
    cudaGetSymbolAddress((void**)&av,  g_av);
    cudaGetSymbolAddress((void**)&ao,  g_ao);
    cudaGetSymbolAddress((void**)&x,   g_x);
    cudaGetSymbolAddress((void**)&xr,  g_xr);
    cudaGetSymbolAddress((void**)&h,   g_h);
    cudaGetSymbolAddress((void**)&f,   g_f);
    cudaGetSymbolAddress((void**)&wr,  g_wr);
    cudaGetSymbolAddress((void**)&rr2, g_rr2);
    cudaGetSymbolAddress((void**)&Wqr, g_Wqr);
    cudaGetSymbolAddress((void**)&Wkr, g_Wkr);
    cudaGetSymbolAddress((void**)&Wvr, g_Wvr);
    cudaGetSymbolAddress((void**)&Wrr, g_Wrr);
    cudaGetSymbolAddress((void**)&Wor, g_Wor);
    cudaGetSymbolAddress((void**)&W1r, g_W1r);
    cudaGetSymbolAddress((void**)&W2r, g_W2r);

    const int M = Bq * Sq;                     // 4096

    // 0) tf32 pre-round of all GEMM inputs that come straight from d_in
    {
        R9 rp;
        const float* srcs[9] = { w, r, (const float*)d_in[4], (const float*)d_in[5],
                                 (const float*)d_in[6], (const float*)d_in[7],
                                 (const float*)d_in[8], (const float*)d_in[11],
                                 (const float*)d_in[13] };
        float* dsts[9] = { wr, rr2, Wqr, Wkr, Wvr, Wrr, Wor, W1r, W2r };
        int ns[9] = { Bq*Sq*Dm, Bq*Sq*Dm, Dm*Dm, Dm*Dm, Dm*Dm, Dm*Dm, Dm*Dm,
                      Dm*DIf, DIf*Dm };
        for (int i = 0; i < 9; i++) {
            rp.seg[i].s = (const float4*)srcs[i];
            rp.seg[i].d = (float4*)dsts[i];
            rp.seg[i].n4 = ns[i] / 4;
        }
        round9_kernel<<<dim3(512, 9), 256>>>(rp);
    }

    // 1) four projections in one launch (z selects)
    {
        Sel4 p{};
        p.A[0] = wr;  p.A[1] = wr;  p.A[2] = wr;  p.A[3] = rr2;
        p.B[0] = Wqr; p.B[1] = Wkr; p.B[2] = Wvr; p.B[3] = Wrr;
        p.C[0] = q;   p.C[1] = k;   p.C[2] = v;   p.C[3] = rr;
        launch_tg<128, false, false, false, true>(dim3(Dm/128, M/128, 4), p,
            Dm, Dm, Dm, Dm, 0,0,0,0,0,0, 1, 1);
    }

    // 2) q + biases (tf32-rounded)
    addbias2_kernel<<<(Bq*Sq*Dm)/256, 256>>>(q, w_bias, r_bias, qw, qr);

    // 3) ac & bd score GEMMs in one launch: per (b,h) [1024,64]@[1024,64]^T
    {
        Sel4 p{};
        p.A[0] = qw; p.A[1] = qr;
        p.B[0] = k;  p.B[1] = rr;
        p.C[0] = ac; p.C[1] = bd;
        launch_tg<128, true, false, false, false>(dim3(Sq/128, Sq/128, 2*Bq*NHh), p,
            DHh, Dm, Dm, Sq,
            (long)Sq*Dm, 64, (long)Sq*Dm, 64, (long)NHh*Sq*Sq, (long)Sq*Sq,
            NHh, Bq*NHh);
    }

    // 4) rel_shift + mask + scale + softmax (probs into ac, tf32-rounded)
    softmax_kernel<<<Bq * NHh * Sq, 256>>>(ac, bd);

    // 5) attn_vec = prob @ v  (batched NN, N=64)
    {
        Sel4 p{};
        p.A[0] = ac; p.B[0] = v; p.C[0] = av;
        launch_tg<64, false, false, false, true>(dim3(1, Sq/128, Bq*NHh), p,
            Sq, Sq, Dm, Dm,
            (long)NHh*Sq*Sq, (long)Sq*Sq, (long)Sq*Dm, 64, (long)Sq*Dm, 64,
            NHh, Bq*NHh);
    }

    // 6) attn_out = attn_vec @ Wo
    {
        Sel4 p{};
        p.A[0] = av; p.B[0] = Wor; p.C[0] = ao;
        launch_tg<128, false, false, false, false>(dim3(Dm/128, M/128, 1), p,
            Dm, Dm, Dm, Dm, 0,0,0,0,0,0, 1, 1);
    }

    // 7) x = LN(w + attn_out); xr = tf32(x)
    ln_kernel<<<M, 256>>>(w, ao, ln1g, ln1b, x, xr);

    // 8) FFN
    {
        Sel4 p{};
        p.A[0] = xr; p.B[0] = W1r; p.C[0] = h; p.bias[0] = b1;
        launch_tg<128, false, true, true, true>(dim3(DIf/128, M/128, 1), p,
            Dm, Dm, DIf, DIf, 0,0,0,0,0,0, 1, 1);
    }
    {
        Sel4 p{};
        p.A[0] = h; p.B[0] = W2r; p.C[0] = f; p.bias[0] = b2;
        launch_tg<128, false, false, true, false>(dim3(Dm/128, M/128, 1), p,
            DIf, DIf, Dm, Dm, 0,0,0,0,0,0, 1, 1);
    }

    // 9) out = LN(x + f)
    ln_kernel<<<M, 256>>>(x, f, ln2g, ln2b, out, nullptr);
}

// round 7
// speedup vs baseline: 3.8885x; 1.2685x over previous
#include <cuda_runtime.h>
#include <math.h>

// Problem constants
#define Bq  4
#define Sq  1024
#define Dm  1024
#define NHh 16
#define DHh 64
#define DIf 4096
#define EPS 1e-5f

// ---------------- scratch (static device globals; no allocations) ----------
__device__ float g_q [Bq*Sq*Dm];
__device__ float g_k [Bq*Sq*Dm];
__device__ float g_v [Bq*Sq*Dm];
__device__ float g_r [Bq*Sq*Dm];
__device__ float g_qw[Bq*Sq*Dm];
__device__ float g_qr[Bq*Sq*Dm];
__device__ float g_av[Bq*Sq*Dm];
__device__ float g_ao[Bq*Sq*Dm];
__device__ float g_x [Bq*Sq*Dm];
__device__ float g_xr[Bq*Sq*Dm];
__device__ float g_h [Bq*Sq*DIf];
__device__ float g_f [Bq*Sq*Dm];
// tf32-rounded copies of inputs
__device__ float g_wr [Bq*Sq*Dm];
__device__ float g_rr2[Bq*Sq*Dm];
__device__ float g_Wqr[Dm*Dm];
__device__ float g_Wkr[Dm*Dm];
__device__ float g_Wvr[Dm*Dm];
__device__ float g_Wrr[Dm*Dm];
__device__ float g_Wor[Dm*Dm];
__device__ float g_W1r[Dm*DIf];
__device__ float g_W2r[DIf*Dm];

// ---------------- tf32 / mma / ldmatrix / cp.async helpers ------------------
__device__ __forceinline__ unsigned f2tf(float v) {
    unsigned r;
    asm("cvt.rna.tf32.f32 %0, %1;" : "=r"(r) : "f"(v));
    return r;
}
__device__ __forceinline__ float roundtf(float v) { return __uint_as_float(f2tf(v)); }

__device__ __forceinline__ void mma_tf32(float* d, const uint4& a, const uint2& b) {
    asm volatile(
        "mma.sync.aligned.m16n8k8.row.col.f32.tf32.tf32.f32 "
        "{%0,%1,%2,%3}, {%4,%5,%6,%7}, {%8,%9}, {%0,%1,%2,%3};"
        : "+f"(d[0]), "+f"(d[1]), "+f"(d[2]), "+f"(d[3])
        : "r"(a.x), "r"(a.y), "r"(a.z), "r"(a.w), "r"(b.x), "r"(b.y));
}

__device__ __forceinline__ uint4 ldsm4(unsigned addr) {
    uint4 d;
    asm volatile("ldmatrix.sync.aligned.m8n8.x4.shared.b16 {%0,%1,%2,%3}, [%4];"
                 : "=r"(d.x), "=r"(d.y), "=r"(d.z), "=r"(d.w) : "r"(addr));
    return d;
}

__device__ __forceinline__ void cp16(unsigned s, const void* g) {
    asm volatile("cp.async.cg.shared.global [%0], [%1], 16;" :: "r"(s), "l"(g));
}
#define CP_COMMIT()   asm volatile("cp.async.commit_group;")
#define CP_WAIT1()    asm volatile("cp.async.wait_group 1;")
#define CP_WAIT_ALL() asm volatile("cp.async.wait_all;" ::: "memory")

// ---------------- TF32 tensor-core GEMM core ---------------------------------
template<int BN, bool TB, bool RELU, bool HASBIAS, bool CVT>
__device__ __forceinline__ void gemm_core(
    const float* __restrict__ Ab, const float* __restrict__ Bb,
    float* __restrict__ Cb, const float* __restrict__ bias,
    int K, int lda, int ldb, int ldc, float* sm)
{
    constexpr int BK = 16;
    constexpr int THREADS = BN * 2;
    constexpr int AS = 20;
    constexpr int BSN = BN + 8;
    constexpr int A_W = 128 * AS;
    constexpr int B_W = TB ? BN * AS : BK * BSN;
    constexpr int A_IT = 512 / THREADS;
    constexpr int B_IT = (4 * BN) / THREADS;

    float* As = sm;
    float* Bs = sm + 3 * A_W;

    const int m0 = blockIdx.y * 128;
    const int n0 = blockIdx.x * BN;
    const int tid  = threadIdx.x;
    const int lane = tid & 31;
    const int wid  = tid >> 5;
    const int warp_m = wid & 1;
    const int warp_n = wid >> 1;

    float acc[4][4][4];
    #pragma unroll
    for (int i = 0; i < 4; i++)
        #pragma unroll
        for (int j = 0; j < 4; j++)
            #pragma unroll
            for (int l = 0; l < 4; l++) acc[i][j][l] = 0.f;

    const unsigned aB = (unsigned)__cvta_generic_to_shared(As);
    const unsigned bB = (unsigned)__cvta_generic_to_shared(Bs);
    const int ntiles = K / BK;

    auto issue = [&](int t, int s) {
        const int k0 = t * BK;
        const unsigned ab = aB + (unsigned)(s * A_W) * 4;
        const unsigned bb = bB + (unsigned)(s * B_W) * 4;
        #pragma unroll
        for (int i = 0; i < A_IT; i++) {
            int e = tid + i * THREADS;
            int row = e >> 2, kk = (e & 3) << 2;
            cp16(ab + (unsigned)(row * AS + kk) * 4,
                 &Ab[(long)(m0 + row) * lda + k0 + kk]);
        }
        #pragma unroll
        for (int i = 0; i < B_IT; i++) {
            int e = tid + i * THREADS;
            if (TB) {
                int n = e >> 2, kk = (e & 3) << 2;
                cp16(bb + (unsigned)(n * AS + kk) * 4,
                     &Bb[(long)(n0 + n) * ldb + k0 + kk]);
            } else {
                int kk = e / (BN / 4), n = (e % (BN / 4)) * 4;
                cp16(bb + (unsigned)(kk * BSN + n) * 4,
                     &Bb[(long)(k0 + kk) * ldb + n0 + n]);
            }
        }
    };

    auto compute = [&](int s) {
        const unsigned ab = aB + (unsigned)(s * A_W) * 4;
        const unsigned bb = bB + (unsigned)(s * B_W) * 4;
        const float* Bw = Bs + s * B_W;
        const int q = lane >> 3, ri = lane & 7;
        #pragma unroll
        for (int ks = 0; ks < 2; ks++) {
            uint4 af[4];
            #pragma unroll
            for (int mt = 0; mt < 4; mt++) {
                int row = warp_m * 64 + mt * 16 + (q & 1) * 8 + ri;
                int col = ks * 8 + (q >> 1) * 4;
                af[mt] = ldsm4(ab + (unsigned)(row * AS + col) * 4);
            }
            uint2 bf[4];
            if (TB) {
                #pragma unroll
                for (int p = 0; p < 2; p++) {
                    int n = warp_n * 32 + p * 16 + (q >> 1) * 8 + ri;
                    int col = ks * 8 + (q & 1) * 4;
                    uint4 d = ldsm4(bb + (unsigned)(n * AS + col) * 4);
                    bf[2*p  ].x = d.x; bf[2*p  ].y = d.y;
                    bf[2*p+1].x = d.z; bf[2*p+1].y = d.w;
                }
            } else {
                const int r = lane >> 2, c = lane & 3;
                #pragma unroll
                for (int nt = 0; nt < 4; nt++) {
                    int n = warp_n * 32 + nt * 8 + r;
                    const float* p = &Bw[(ks * 8 + c) * BSN + n];
                    bf[nt].x = __float_as_uint(p[0]);
                    bf[nt].y = __float_as_uint(p[4 * BSN]);
                }
            }
            #pragma unroll
            for (int mt = 0; mt < 4; mt++)
                #pragma unroll
                for (int nt = 0; nt < 4; nt++)
                    mma_tf32(acc[mt][nt], af[mt], bf[nt]);
        }
    };

    issue(0, 0); CP_COMMIT();
    if (ntiles > 1) issue(1, 1);
    CP_COMMIT();
    for (int t = 0; t < ntiles; t++) {
        CP_WAIT1();
        __syncthreads();
        if (t + 2 < ntiles) issue(t + 2, (t + 2) % 3);
        CP_COMMIT();
        compute(t % 3);
    }

    #pragma unroll
    for (int mt = 0; mt < 4; mt++) {
        int rbase = m0 + warp_m * 64 + mt * 16 + (lane >> 2);
        #pragma unroll
        for (int nt = 0; nt < 4; nt++) {
            int cbase = n0 + warp_n * 32 + nt * 8 + (lane & 3) * 2;
            float* d = acc[mt][nt];
            float b0 = 0.f, b1 = 0.f;
            if (HASBIAS) { b0 = bias[cbase]; b1 = bias[cbase + 1]; }
            float v0 = d[0] + b0, v1 = d[1] + b1;
            float v2 = d[2] + b0, v3 = d[3] + b1;
            if (RELU) {
                v0 = fmaxf(v0, 0.f); v1 = fmaxf(v1, 0.f);
                v2 = fmaxf(v2, 0.f); v3 = fmaxf(v3, 0.f);
            }
            if (CVT) {
                v0 = roundtf(v0); v1 = roundtf(v1);
                v2 = roundtf(v2); v3 = roundtf(v3);
            }
            *(float2*)&Cb[(long)rbase * ldc + cbase]       = make_float2(v0, v1);
            *(float2*)&Cb[(long)(rbase + 8) * ldc + cbase] = make_float2(v2, v3);
        }
    }
}

// ---------------- wrapper with pointer-select batching -----------------------
struct Sel4 {
    const float* A[4]; const float* B[4]; float* C[4]; const float* bias[4];
};

template<int BN, bool TB, bool RELU, bool HASBIAS, bool CVT>
__global__ void __launch_bounds__(BN*2)
tg(Sel4 p, int K, int lda, int ldb, int ldc,
   long offA1, long offA2, long offB1, long offB2, long offC1, long offC2,
   int nh, int bps)
{
    extern __shared__ float sm[];
    const int z = blockIdx.z;
    const int sel = z / bps, b = z - sel * bps;
    const float* Ab = p.A[sel] + (long)(b / nh) * offA1 + (long)(b % nh) * offA2;
    const float* Bb = p.B[sel] + (long)(b / nh) * offB1 + (long)(b % nh) * offB2;
    float*       Cb = p.C[sel] + (long)(b / nh) * offC1 + (long)(b % nh) * offC2;
    gemm_core<BN, TB, RELU, HASBIAS, CVT>(Ab, Bb, Cb, p.bias[sel],
                                          K, lda, ldb, ldc, sm);
}

template<int BN, bool TB, bool RELU, bool HASBIAS, bool CVT>
static void launch_tg(dim3 grid, const Sel4& p, int K, int lda, int ldb, int ldc,
                      long oA1, long oA2, long oB1, long oB2, long oC1, long oC2,
                      int nh, int bps)
{
    constexpr int smem = 3 * (128 * 20 + (TB ? BN * 20 : 16 * (BN + 8))) * 4;
    cudaFuncSetAttribute(tg<BN, TB, RELU, HASBIAS, CVT>,
                         cudaFuncAttributeMaxDynamicSharedMemorySize, smem);
    tg<BN, TB, RELU, HASBIAS, CVT><<<grid, BN * 2, smem>>>(
        p, K, lda, ldb, ldc, oA1, oA2, oB1, oB2, oC1, oC2, nh, bps);
}

// ---------------- fused flash attention with rel-shift -----------------------
// One CTA = 128 query rows of one (b,h). Online softmax, no S materialization.
// smem floats: K_s[64][68] | Vt[64][68] | rr_s[200][68] | Pb[128][68]
#define FL_ST 68
#define FL_KS 0
#define FL_VT 4352
#define FL_RR 8704
#define FL_PB 22304
#define FL_TOT 31008

__global__ void __launch_bounds__(256, 1)
flash_kernel(const float* __restrict__ qwp, const float* __restrict__ qrp,
             const float* __restrict__ kp,  const float* __restrict__ rp,
             const float* __restrict__ vp,  float* __restrict__ avp)
{
    extern __shared__ float sm[];
    float* Vt = sm + FL_VT;
    float* Pb = sm + FL_PB;

    const int bid = blockIdx.x;
    const int it  = 7 - (bid >> 6);           // heavy blocks first
    const int bh  = bid & 63;
    const int b   = bh >> 4, h = bh & 15;
    const int i0  = it * 128;

    const int tid = threadIdx.x, lane = tid & 31, wid = tid >> 5;
    const int r0w = wid * 16;                 // this warp's 16 query rows
    const int grp = lane >> 3, rw = lane & 7; // ldmatrix addressing
    const int r = lane >> 2, c = lane & 3;    // accumulator coords

    const long qbase  = ((long)(b * Sq + i0)) * Dm + h * 64;
    const long kvbase = ((long)b * Sq) * Dm + h * 64;

    const unsigned sK = (unsigned)__cvta_generic_to_shared(sm + FL_KS);
    const unsigned sV = (unsigned)__cvta_generic_to_shared(sm + FL_VT);
    const unsigned sR = (unsigned)__cvta_generic_to_shared(sm + FL_RR);
    const unsigned sP = (unsigned)__cvta_generic_to_shared(sm + FL_PB);

    // ---- stage Q tiles (qw -> rr_s, qr -> Pb) and extract fragments ----
    uint4 qwf[8], qrf[8];
    for (int e = tid; e < 128 * 16; e += 256) {
        int row = e >> 4, c4 = (e & 15) << 2;
        cp16(sR + (unsigned)(row * FL_ST + c4) * 4, &qwp[qbase + (long)row * Dm + c4]);
        cp16(sP + (unsigned)(row * FL_ST + c4) * 4, &qrp[qbase + (long)row * Dm + c4]);
    }
    CP_COMMIT(); CP_WAIT_ALL(); __syncthreads();
    #pragma unroll
    for (int ks = 0; ks < 8; ks++) {
        unsigned off = (unsigned)((r0w + (grp & 1) * 8 + rw) * FL_ST + ks * 8 + (grp >> 1) * 4) * 4;
        qwf[ks] = ldsm4(sR + off);
        qrf[ks] = ldsm4(sP + off);
    }

    float m0v = -1e30f, m1v = -1e30f, l0v = 0.f, l1v = 0.f;
    float o_[8][4];
    #pragma unroll
    for (int i = 0; i < 8; i++)
        #pragma unroll
        for (int j = 0; j < 4; j++) o_[i][j] = 0.f;

    const int njt = (i0 >> 6) + 2;
    for (int jt = 0; jt < njt; jt++) {
        const int j0 = jt * 64;
        const int l0 = Sq - 128 + j0 - i0;    // rr window base (>= 0 always)
        __syncthreads();                       // prev-tile smem reads done

        // K tile + rr window via cp.async
        for (int e = tid; e < 64 * 16; e += 256) {
            int row = e >> 4, c4 = (e & 15) << 2;
            cp16(sK + (unsigned)(row * FL_ST + c4) * 4,
                 &kp[kvbase + (long)(j0 + row) * Dm + c4]);
        }
        for (int e = tid; e < 192 * 16; e += 256) {
            int row = e >> 4, c4 = (e & 15) << 2;
            int lr = l0 + row; if (lr > Sq - 1) lr = Sq - 1;   // clamp; masked anyway
            cp16(sR + (unsigned)(row * FL_ST + c4) * 4,
                 &rp[kvbase + (long)lr * Dm + c4]);
        }
        CP_COMMIT();
        // V tile: LDG + transposed STS -> Vt[d][j]
        {
            int jj = tid >> 2, db = (tid & 3) << 4;
            const float* vrow = &vp[kvbase + (long)(j0 + jj) * Dm + db];
            #pragma unroll
            for (int u = 0; u < 4; u++) {
                float4 t = *(const float4*)(vrow + u * 4);
                Vt[(db + u * 4 + 0) * FL_ST + jj] = t.x;
                Vt[(db + u * 4 + 1) * FL_ST + jj] = t.y;
                Vt[(db + u * 4 + 2) * FL_ST + jj] = t.z;
                Vt[(db + u * 4 + 3) * FL_ST + jj] = t.w;
            }
        }
        CP_WAIT_ALL(); __syncthreads();

        // ---- E band MMA: E[ii][d_win] -> scatter band (ii, jj=d-127+ii) ----
        {
            int dlo = 105 - r0w; if (dlo < 0) dlo = 0; dlo &= ~7;
            int dhi = (190 - r0w) & ~7;
            for (int d0 = dlo; d0 <= dhi; d0 += 16) {
                bool has2 = (d0 + 8 <= dhi);
                float e0[4] = {0.f,0.f,0.f,0.f}, e1[4] = {0.f,0.f,0.f,0.f};
                #pragma unroll
                for (int ks = 0; ks < 8; ks++) {
                    uint4 bf = ldsm4(sR + (unsigned)((d0 + (grp >> 1) * 8 + rw) * FL_ST
                                                     + ks * 8 + (grp & 1) * 4) * 4);
                    mma_tf32(e0, qrf[ks], make_uint2(bf.x, bf.y));
                    if (has2) mma_tf32(e1, qrf[ks], make_uint2(bf.z, bf.w));
                }
                int ii0 = r0w + r, ii1 = ii0 + 8;
                int d = d0 + 2 * c;
                int ja = d - 127 + ii0, jb = d - 127 + ii1;
                if (ja     >= 0 && ja     < 64) Pb[ii0 * FL_ST + ja    ] = e0[0];
                if (ja + 1 >= 0 && ja + 1 < 64) Pb[ii0 * FL_ST + ja + 1] = e0[1];
                if (jb     >= 0 && jb     < 64) Pb[ii1 * FL_ST + jb    ] = e0[2];
                if (jb + 1 >= 0 && jb + 1 < 64) Pb[ii1 * FL_ST + jb + 1] = e0[3];
                if (has2) {
                    int ja2 = ja + 8, jb2 = jb + 8;
                    if (ja2     >= 0 && ja2     < 64) Pb[ii0 * FL_ST + ja2    ] = e1[0];
                    if (ja2 + 1 >= 0 && ja2 + 1 < 64) Pb[ii0 * FL_ST + ja2 + 1] = e1[1];
                    if (jb2     >= 0 && jb2     < 64) Pb[ii1 * FL_ST + jb2    ] = e1[2];
                    if (jb2 + 1 >= 0 && jb2 + 1 < 64) Pb[ii1 * FL_ST + jb2 + 1] = e1[3];
                }
            }
        }
        __syncwarp();   // band written by this warp's lanes, read below

        // ---- ac MMA ----
        float s_[8][4];
        #pragma unroll
        for (int i = 0; i < 8; i++)
            #pragma unroll
            for (int j = 0; j < 4; j++) s_[i][j] = 0.f;
        #pragma unroll
        for (int ks = 0; ks < 8; ks++) {
            #pragma unroll
            for (int p = 0; p < 4; p++) {
                uint4 bf = ldsm4(sK + (unsigned)((p * 16 + (grp >> 1) * 8 + rw) * FL_ST
                                                 + ks * 8 + (grp & 1) * 4) * 4);
                mma_tf32(s_[2 * p],     qwf[ks], make_uint2(bf.x, bf.y));
                mma_tf32(s_[2 * p + 1], qwf[ks], make_uint2(bf.z, bf.w));
            }
        }

        // ---- S = (ac + E)*scale, mask, online softmax ----
        const int gi0 = i0 + r0w + r, gi1 = gi0 + 8;
        float mx0 = -1e30f, mx1 = -1e30f;
        #pragma unroll
        for (int nt = 0; nt < 8; nt++) {
            int jj = nt * 8 + 2 * c, jg = j0 + jj;
            float e00 = Pb[(r0w + r) * FL_ST + jj],     e01 = Pb[(r0w + r) * FL_ST + jj + 1];
            float e10 = Pb[(r0w + r + 8) * FL_ST + jj], e11 = Pb[(r0w + r + 8) * FL_ST + jj + 1];
            s_[nt][0] = (jg     <= gi0) ? (s_[nt][0] + e00) * 0.125f : -1e30f;
            s_[nt][1] = (jg + 1 <= gi0) ? (s_[nt][1] + e01) * 0.125f : -1e30f;
            s_[nt][2] = (jg     <= gi1) ? (s_[nt][2] + e10) * 0.125f : -1e30f;
            s_[nt][3] = (jg + 1 <= gi1) ? (s_[nt][3] + e11) * 0.125f : -1e30f;
            mx0 = fmaxf(mx0, fmaxf(s_[nt][0], s_[nt][1]));
            mx1 = fmaxf(mx1, fmaxf(s_[nt][2], s_[nt][3]));
        }
        mx0 = fmaxf(mx0, __shfl_xor_sync(0xffffffffu, mx0, 1));
        mx0 = fmaxf(mx0, __shfl_xor_sync(0xffffffffu, mx0, 2));
        mx1 = fmaxf(mx1, __shfl_xor_sync(0xffffffffu, mx1, 1));
        mx1 = fmaxf(mx1, __shfl_xor_sync(0xffffffffu, mx1, 2));
        float mn0 = fmaxf(m0v, mx0), mn1 = fmaxf(m1v, mx1);
        float a0 = __expf(m0v - mn0), a1 = __expf(m1v - mn1);
        float sum0 = 0.f, sum1 = 0.f;
        #pragma unroll
        for (int nt = 0; nt < 8; nt++) {
            int jj = nt * 8 + 2 * c;
            float p00 = __expf(s_[nt][0] - mn0), p01 = __expf(s_[nt][1] - mn0);
            float p10 = __expf(s_[nt][2] - mn1), p11 = __expf(s_[nt][3] - mn1);
            sum0 += p00 + p01; sum1 += p10 + p11;
            Pb[(r0w + r) * FL_ST + jj]         = roundtf(p00);
            Pb[(r0w + r) * FL_ST + jj + 1]     = roundtf(p01);
            Pb[(r0w + r + 8) * FL_ST + jj]     = roundtf(p10);
            Pb[(r0w + r + 8) * FL_ST + jj + 1] = roundtf(p11);
        }
        sum0 += __shfl_xor_sync(0xffffffffu, sum0, 1);
        sum0 += __shfl_xor_sync(0xffffffffu, sum0, 2);
        sum1 += __shfl_xor_sync(0xffffffffu, sum1, 1);
        sum1 += __shfl_xor_sync(0xffffffffu, sum1, 2);
        l0v = l0v * a0 + sum0; l1v = l1v * a1 + sum1;
        m0v = mn0; m1v = mn1;
        #pragma unroll
        for (int dt = 0; dt < 8; dt++) {
            o_[dt][0] *= a0; o_[dt][1] *= a0;
            o_[dt][2] *= a1; o_[dt][3] *= a1;
        }
        __syncwarp();   // P written by this warp, read via ldmatrix below

        // ---- PV: O += P @ V ----
        #pragma unroll
        for (int ks = 0; ks < 8; ks++) {
            uint4 af = ldsm4(sP + (unsigned)((r0w + (grp & 1) * 8 + rw) * FL_ST
                                             + ks * 8 + (grp >> 1) * 4) * 4);
            #pragma unroll
            for (int p = 0; p < 4; p++) {
                uint4 bf = ldsm4(sV + (unsigned)((p * 16 + (grp >> 1) * 8 + rw) * FL_ST
                                                 + ks * 8 + (grp & 1) * 4) * 4);
                mma_tf32(o_[2 * p],     af, make_uint2(bf.x, bf.y));
                mma_tf32(o_[2 * p + 1], af, make_uint2(bf.z, bf.w));
            }
        }
    }

    // ---- epilogue: O / l, tf32-rounded (feeds Wo GEMM) ----
    float i0v = 1.f / l0v, i1v = 1.f / l1v;
    long ob0 = ((long)(b * Sq + i0 + r0w + r)) * Dm + h * 64;
    long ob1 = ob0 + 8L * Dm;
    #pragma unroll
    for (int dt = 0; dt < 8; dt++) {
        int d = dt * 8 + 2 * c;
        *(float2*)&avp[ob0 + d] = make_float2(roundtf(o_[dt][0] * i0v), roundtf(o_[dt][1] * i0v));
        *(float2*)&avp[ob1 + d] = make_float2(roundtf(o_[dt][2] * i1v), roundtf(o_[dt][3] * i1v));
    }
}

// ---------------- input tf32 pre-round pass ---------------------------------
struct RSeg { const float4* s; float4* d; int n4; };
struct R9   { RSeg seg[9]; };

__global__ void round9_kernel(R9 r) {
    RSeg sg = r.seg[blockIdx.y];
    for (int i = blockIdx.x * blockDim.x + threadIdx.x; i < sg.n4;
         i += gridDim.x * blockDim.x) {
        float4 v = sg.s[i];
        v.x = roundtf(v.x); v.y = roundtf(v.y);
        v.z = roundtf(v.z); v.w = roundtf(v.w);
        sg.d[i] = v;
    }
}

// ---------------- reductions ----------------------------------------------
__device__ __forceinline__ float warpSum(float v) {
    #pragma unroll
    for (int o = 16; o > 0; o >>= 1) v += __shfl_xor_sync(0xffffffffu, v, o);
    return v;
}
__device__ float blockSum(float v) {
    __shared__ float red[8];
    __syncthreads();
    int lane = threadIdx.x & 31, wid = threadIdx.x >> 5;
    v = warpSum(v);
    if (lane == 0) red[wid] = v;
    __syncthreads();
    if (wid == 0) {
        float t = (lane < 8) ? red[lane] : 0.f;
        t = warpSum(t);
        if (lane == 0) red[0] = t;
    }
    __syncthreads();
    return red[0];
}

// ---------------- q + bias broadcast (tf32-rounded outputs) -----------------
__global__ void addbias2_kernel(const float* __restrict__ q,
                                const float* __restrict__ wb,
                                const float* __restrict__ rb,
                                float* __restrict__ qw,
                                float* __restrict__ qr)
{
    int t = blockIdx.x * blockDim.x + threadIdx.x;
    float v = q[t];
    int c = t & (Dm - 1);
    qw[t] = roundtf(v + wb[c]);
    qr[t] = roundtf(v + rb[c]);
}

// ---------------- fused residual + LayerNorm (optional tf32 copy) -----------
__global__ void ln_kernel(const float* __restrict__ a, const float* __restrict__ b,
                          const float* __restrict__ gam, const float* __restrict__ bet,
                          float* __restrict__ out, float* __restrict__ out_tf)
{
    const long row = blockIdx.x;
    const long base = row * Dm;
    __shared__ float sbuf[Dm];
    const int tid = threadIdx.x;

    float ls = 0.f;
    for (int j = tid; j < Dm; j += blockDim.x) {
        float x = a[base + j] + b[base + j];
        sbuf[j] = x;
        ls += x;
    }
    float mu = blockSum(ls) * (1.f / Dm);

    float lv = 0.f;
    for (int j = tid; j < Dm; j += blockDim.x) {
        float d = sbuf[j] - mu;
        lv += d * d;
    }
    float var = blockSum(lv) * (1.f / Dm);
    float inv = rsqrtf(var + EPS);

    for (int j = tid; j < Dm; j += blockDim.x) {
        float y = (sbuf[j] - mu) * inv * gam[j] + bet[j];
        out[base + j] = y;
        if (out_tf) out_tf[base + j] = roundtf(y);
    }
}

// ---------------- launch ----------------------------------------------------
extern "C" void kernel_launch(void* const* d_in, const int* in_sizes, int n_in,
                              void* d_out, int out_size)
{
    const float* w      = (const float*)d_in[0];
    const float* r      = (const float*)d_in[1];
    const float* w_bias = (const float*)d_in[2];
    const float* r_bias = (const float*)d_in[3];
    const float* b1     = (const float*)d_in[12];
    const float* b2     = (const float*)d_in[14];
    const float* ln1g   = (const float*)d_in[9];
    const float* ln1b   = (const float*)d_in[10];
    const float* ln2g   = (const float*)d_in[15];
    const float* ln2b   = (const float*)d_in[16];
    float* out = (float*)d_out;

    float *q, *k, *v, *rr, *qw, *qr, *av, *ao, *x, *xr, *h, *f;
    float *wr, *rr2, *Wqr, *Wkr, *Wvr, *Wrr, *Wor, *W1r, *W2r;
    cudaGetSymbolAddress((void**)&q,   g_q);
    cudaGetSymbolAddress((void**)&k,   g_k);
    cudaGetSymbolAddress((void**)&v,   g_v);
    cudaGetSymbolAddress((void**)&rr,  g_r);
    cudaGetSymbolAddress((void**)&qw,  g_qw);
    cudaGetSymbolAddress((void**)&qr,  g_qr);
    cudaGetSymbolAddress((void**)&av,  g_av);
    cudaGetSymbolAddress((void**)&ao,  g_ao);
    cudaGetSymbolAddress((void**)&x,   g_x);
    cudaGetSymbolAddress((void**)&xr,  g_xr);
    cudaGetSymbolAddress((void**)&h,   g_h);
    cudaGetSymbolAddress((void**)&f,   g_f);
    cudaGetSymbolAddress((void**)&wr,  g_wr);
    cudaGetSymbolAddress((void**)&rr2, g_rr2);
    cudaGetSymbolAddress((void**)&Wqr, g_Wqr);
    cudaGetSymbolAddress((void**)&Wkr, g_Wkr);
    cudaGetSymbolAddress((void**)&Wvr, g_Wvr);
    cudaGetSymbolAddress((void**)&Wrr, g_Wrr);
    cudaGetSymbolAddress((void**)&Wor, g_Wor);
    cudaGetSymbolAddress((void**)&W1r, g_W1r);
    cudaGetSymbolAddress((void**)&W2r, g_W2r);

    const int M = Bq * Sq;

    // 0) tf32 pre-round of raw inputs
    {
        R9 rp;
        const float* srcs[9] = { w, r, (const float*)d_in[4], (const float*)d_in[5],
                                 (const float*)d_in[6], (const float*)d_in[7],
                                 (const float*)d_in[8], (const float*)d_in[11],
                                 (const float*)d_in[13] };
        float* dsts[9] = { wr, rr2, Wqr, Wkr, Wvr, Wrr, Wor, W1r, W2r };
        int ns[9] = { Bq*Sq*Dm, Bq*Sq*Dm, Dm*Dm, Dm*Dm, Dm*Dm, Dm*Dm, Dm*Dm,
                      Dm*DIf, DIf*Dm };
        for (int i = 0; i < 9; i++) {
            rp.seg[i].s = (const float4*)srcs[i];
            rp.seg[i].d = (float4*)dsts[i];
            rp.seg[i].n4 = ns[i] / 4;
        }
        round9_kernel<<<dim3(512, 9), 256>>>(rp);
    }

    // 1) four projections in one launch
    {
        Sel4 p{};
        p.A[0] = wr;  p.A[1] = wr;  p.A[2] = wr;  p.A[3] = rr2;
        p.B[0] = Wqr; p.B[1] = Wkr; p.B[2] = Wvr; p.B[3] = Wrr;
        p.C[0] = q;   p.C[1] = k;   p.C[2] = v;   p.C[3] = rr;
        launch_tg<128, false, false, false, true>(dim3(Dm/128, M/128, 4), p,
            Dm, Dm, Dm, Dm, 0,0,0,0,0,0, 1, 1);
    }

    // 2) q + biases (tf32-rounded)
    addbias2_kernel<<<(Bq*Sq*Dm)/256, 256>>>(q, w_bias, r_bias, qw, qr);

    // 3) fused flash attention (replaces score GEMMs + softmax + AV GEMM)
    cudaFuncSetAttribute(flash_kernel,
                         cudaFuncAttributeMaxDynamicSharedMemorySize, FL_TOT * 4);
    flash_kernel<<<512, 256, FL_TOT * 4>>>(qw, qr, k, rr, v, av);

    // 4) attn_out = attn_vec @ Wo
    {
        Sel4 p{};
        p.A[0] = av; p.B[0] = Wor; p.C[0] = ao;
        launch_tg<128, false, false, false, false>(dim3(Dm/128, M/128, 1), p,
            Dm, Dm, Dm, Dm, 0,0,0,0,0,0, 1, 1);
    }

    // 5) x = LN(w + attn_out); xr = tf32(x)
    ln_kernel<<<M, 256>>>(w, ao, ln1g, ln1b, x, xr);

    // 6) FFN
    {
        Sel4 p{};
        p.A[0] = xr; p.B[0] = W1r; p.C[0] = h; p.bias[0] = b1;
        launch_tg<128, false, true, true, true>(dim3(DIf/128, M/128, 1), p,
            Dm, Dm, DIf, DIf, 0,0,0,0,0,0, 1, 1);
    }
    {
        Sel4 p{};
        p.A[0] = h; p.B[0] = W2r; p.C[0] = f; p.bias[0] = b2;
        launch_tg<128, false, false, true, false>(dim3(Dm/128, M/128, 1), p,
            DIf, DIf, Dm, Dm, 0,0,0,0,0,0, 1, 1);
    }

    // 7) out = LN(x + f)
    ln_kernel<<<M, 256>>>(x, f, ln2g, ln2b, out, nullptr);
}